// round 8
// baseline (speedup 1.0000x reference)
#include <cuda_runtime.h>

// ---------------------------------------------------------------------------
// NeuralODE Tsit5 — persistent fused kernel, v8 "zero-sync warps".
// CTA = 16 batch rows, 128 threads (4 warps). All weights in SMEM (shared,
// read-only). Each warp owns 4 batch rows END-TO-END: prologue, 3 layers,
// k-buffers, y-update. No __syncthreads in the hot loop — only __syncwarp.
// Lane tile: 4 rows x 4 cols (N=128) / 4 rows x 2 cols (N=64), f32x2 FMA.
// ---------------------------------------------------------------------------

#define NTHREADS 128
#define M_TILE   16

__constant__ float d_cs[6] = {0.0f, 0.161f, 0.327f, 0.9f, 0.9800255409045097f, 1.0f};
__constant__ float d_A[6][5] = {
    {0.f, 0.f, 0.f, 0.f, 0.f},
    {0.161f, 0.f, 0.f, 0.f, 0.f},
    {-0.008480655492356989f, 0.335480655492357f, 0.f, 0.f, 0.f},
    {2.8971530571054935f, -6.359448489975075f, 4.3622954328695815f, 0.f, 0.f},
    {5.325864828439257f, -11.748883564062828f, 7.4955393428898365f, -0.09249506636175525f, 0.f},
    {5.86145544294642f, -12.92096931784711f, 8.159367898576159f, -0.071584973281401f, -0.028269050394068383f}
};
__constant__ float d_B[6] = {
    0.09646076681806523f, 0.01f, 0.4798896504144996f,
    1.379008574103742f, -3.290069515436081f, 2.324710524099774f
};

// ---- f32x2 helpers ---------------------------------------------------------
__device__ __forceinline__ unsigned long long pack2(float x, float y) {
    unsigned long long r;
    asm("mov.b64 %0, {%1, %2};" : "=l"(r) : "f"(x), "f"(y));
    return r;
}
__device__ __forceinline__ float2 unpack2(unsigned long long v) {
    float2 f;
    asm("mov.b64 {%0, %1}, %2;" : "=f"(f.x), "=f"(f.y) : "l"(v));
    return f;
}
__device__ __forceinline__ void ffma2(unsigned long long& d,
                                      unsigned long long a,
                                      unsigned long long b) {
    asm("fma.rn.f32x2 %0, %1, %2, %0;" : "+l"(d) : "l"(a), "l"(b));
}

// ---- sizes (floats) ---------------------------------------------------------
#define KP0 36      // layer0 k-pairs: 72 = t + 64 y + 7 zero pad
#define KP1 64
#define KP2 64
#define SA0 72
#define SA1 132
#define SKB 66
// per-warp scratch block (floats):
//   act0 4*SA0 @0, act1 4*SA1 @288, act2 4*SA1 @816,
//   kbuf 6*4*SKB @1344, ysh 4*64 @2928  -> total 3184
#define WBLK   3184
#define O_ACT1 288
#define O_ACT2 816
#define O_KB   1344
#define O_Y    2928

#define U64_WORDS (KP0*128 + KP1*128 + KP2*64)
#define F32_WORDS (128 + 128 + 64 + 4*WBLK)
#define SMEM_BYTES (U64_WORDS*8 + F32_WORDS*4)   // ~183 KB

// ---- one warp-local MLP layer ----------------------------------------------
// Warp computes out[4][N] = act[4][K] @ W^T + b for ITS 4 rows, full K.
// Lane owns CT = N/32 consecutive output cols at c0 = lane*CT.
template<int N, int CT, int KP, int SIN, int SOUT, bool RELU>
__device__ __forceinline__ void warp_layer(const float* __restrict__ aW,
                                           const unsigned long long* __restrict__ wp,
                                           const float* __restrict__ bias,
                                           float* __restrict__ oW, int lane) {
    const int c0 = lane * CT;
    const unsigned long long* wr = wp + c0;

    unsigned long long acc[4][CT];
#pragma unroll
    for (int i = 0; i < 4; i++)
#pragma unroll
        for (int j = 0; j < CT; j++) acc[i][j] = 0ull;

#pragma unroll 4
    for (int kp = 0; kp < KP; kp++) {
        unsigned long long a[4];
#pragma unroll
        for (int i = 0; i < 4; i++)   // broadcast loads (all lanes same addr)
            a[i] = *reinterpret_cast<const unsigned long long*>(aW + i * SIN + 2 * kp);
        unsigned long long wv[CT];
        if constexpr (CT == 4) {
            ulonglong2 wA = *reinterpret_cast<const ulonglong2*>(wr + kp * N);
            ulonglong2 wB = *reinterpret_cast<const ulonglong2*>(wr + kp * N + 2);
            wv[0] = wA.x; wv[1] = wA.y; wv[2] = wB.x; wv[3] = wB.y;
        } else {
            ulonglong2 wA = *reinterpret_cast<const ulonglong2*>(wr + kp * N);
            wv[0] = wA.x; wv[1] = wA.y;
        }
#pragma unroll
        for (int j = 0; j < CT; j++)
#pragma unroll
            for (int i = 0; i < 4; i++) ffma2(acc[i][j], a[i], wv[j]);
    }

    // epilogue: horizontal add + bias (+ReLU), vector store
    float bv[CT];
#pragma unroll
    for (int j = 0; j < CT; j++) bv[j] = bias[c0 + j];
#pragma unroll
    for (int i = 0; i < 4; i++) {
        float v[CT];
#pragma unroll
        for (int j = 0; j < CT; j++) {
            float2 p = unpack2(acc[i][j]);
            v[j] = p.x + p.y + bv[j];
            if (RELU) v[j] = fmaxf(v[j], 0.f);
        }
        if constexpr (CT == 4)
            *reinterpret_cast<float4*>(oW + i * SOUT + c0) =
                make_float4(v[0], v[1], v[2], v[3]);
        else
            *reinterpret_cast<float2*>(oW + i * SOUT + c0) = make_float2(v[0], v[1]);
    }
}

// ---------------------------------------------------------------------------
__global__ void __launch_bounds__(NTHREADS, 1)
node_kernel(const float* __restrict__ y0, const float* __restrict__ ts,
            const float* __restrict__ w0, const float* __restrict__ b0,
            const float* __restrict__ w1, const float* __restrict__ b1,
            const float* __restrict__ w2, const float* __restrict__ b2,
            float* __restrict__ out, int T) {
    extern __shared__ unsigned long long smem_u64[];
    unsigned long long* wp0 = smem_u64;
    unsigned long long* wp1 = wp0 + KP0 * 128;
    unsigned long long* wp2 = wp1 + KP1 * 128;
    float* fb  = reinterpret_cast<float*>(wp2 + KP2 * 64);
    float* sb0 = fb;           fb += 128;
    float* sb1 = fb;           fb += 128;
    float* sb2 = fb;           fb += 64;
    float* wsp = fb;           // 4 * WBLK per-warp scratch

    const int tid  = threadIdx.x;
    const int lane = tid & 31;
    const int warp = tid >> 5;               // 0..3, owns rows warp*4..+3
    const int row0 = blockIdx.x * M_TILE;

    // per-warp scratch pointers
    float* act0W = wsp + warp * WBLK;
    float* act1W = act0W + O_ACT1;
    float* act2W = act0W + O_ACT2;
    float* kbW   = act0W + O_KB;             // [6][4][SKB]
    float* yW    = act0W + O_Y;              // [4][64]

    // ---- one-time setup: packed transposed weights, biases, y, pads --------
    for (int idx = tid; idx < KP0 * 128; idx += NTHREADS) {
        int kp = idx >> 7, n = idx & 127;
        int k0 = 2 * kp, k1 = 2 * kp + 1;
        float a = (k0 < 65) ? w0[n * 65 + k0] : 0.0f;
        float b = (k1 < 65) ? w0[n * 65 + k1] : 0.0f;
        wp0[idx] = pack2(a, b);
    }
    for (int idx = tid; idx < KP1 * 128; idx += NTHREADS) {
        int kp = idx >> 7, n = idx & 127;
        wp1[idx] = pack2(w1[n * 128 + 2 * kp], w1[n * 128 + 2 * kp + 1]);
    }
    for (int idx = tid; idx < KP2 * 64; idx += NTHREADS) {
        int kp = idx >> 6, n = idx & 63;
        wp2[idx] = pack2(w2[n * 128 + 2 * kp], w2[n * 128 + 2 * kp + 1]);
    }
    for (int idx = tid; idx < 128; idx += NTHREADS) { sb0[idx] = b0[idx]; sb1[idx] = b1[idx]; }
    for (int idx = tid; idx < 64;  idx += NTHREADS) sb2[idx] = b2[idx];
    // y0 -> per-warp ysh slots
    for (int idx = tid; idx < M_TILE * 64; idx += NTHREADS) {
        int r = idx >> 6, c = idx & 63;
        wsp[(r >> 2) * WBLK + O_Y + (r & 3) * 64 + c] = y0[row0 * 64 + idx];
    }
    // zero act0 K-pad cols 65..71 for all 16 rows
    if (tid < M_TILE) {
        float* a0 = wsp + (tid >> 2) * WBLK + (tid & 3) * SA0;
#pragma unroll
        for (int kk = 65; kk < 72; kk++) a0[kk] = 0.0f;
    }
    __syncthreads();   // last CTA-wide barrier before the zero-sync hot loop

    const float dt = ts[1] - ts[0];
    const int steps = T - 1;

    for (int st = 0; st < steps; st++) {
        const float t = (float)st * dt;
        for (int s = 0; s < 6; s++) {
            // ---- prologue (warp-local): act0 = [t_s, y + dt*sum A k, pad] ---
            const float ts_ = fmaf(d_cs[s], dt, t);
            if (lane == 0) {
#pragma unroll
                for (int i = 0; i < 4; i++) act0W[i * SA0] = ts_;
            }
#pragma unroll
            for (int i = 0; i < 4; i++)
#pragma unroll
                for (int q = 0; q < 2; q++) {
                    const int c = 2 * lane + q;
                    float acc = 0.0f;
                    for (int j = 0; j < s; j++)
                        acc = fmaf(d_A[s][j], kbW[j * (4 * SKB) + i * SKB + c], acc);
                    act0W[i * SA0 + 1 + c] = fmaf(dt, acc, yW[i * 64 + c]);
                }
            __syncwarp();
            warp_layer<128, 4, KP0, SA0, SA1, true >(act0W, wp0, sb0, act1W, lane);
            __syncwarp();
            warp_layer<128, 4, KP1, SA1, SA1, true >(act1W, wp1, sb1, act2W, lane);
            __syncwarp();
            warp_layer<64,  2, KP2, SA1, SKB, false>(act2W, wp2, sb2,
                                                     kbW + s * (4 * SKB), lane);
            __syncwarp();
        }
        // ---- y += dt * sum_j B[j] k_j (warp-local) ----
#pragma unroll
        for (int i = 0; i < 4; i++)
#pragma unroll
            for (int q = 0; q < 2; q++) {
                const int c = 2 * lane + q;
                float acc = d_B[0] * kbW[i * SKB + c];
#pragma unroll
                for (int j = 1; j < 6; j++)
                    acc = fmaf(d_B[j], kbW[j * (4 * SKB) + i * SKB + c], acc);
                yW[i * 64 + c] = fmaf(dt, acc, yW[i * 64 + c]);
            }
        __syncwarp();
    }

    // ---- write back this warp's 4 rows ----
#pragma unroll
    for (int i = 0; i < 4; i++)
#pragma unroll
        for (int q = 0; q < 2; q++) {
            const int c = 2 * lane + q;
            out[(row0 + warp * 4 + i) * 64 + c] = yW[i * 64 + c];
        }
}

// ---------------------------------------------------------------------------
extern "C" void kernel_launch(void* const* d_in, const int* in_sizes, int n_in,
                              void* d_out, int out_size) {
    const float* y0 = (const float*)d_in[0];
    const float* ts = (const float*)d_in[1];
    const float* w0 = (const float*)d_in[2];
    const float* b0 = (const float*)d_in[3];
    const float* w1 = (const float*)d_in[4];
    const float* b1 = (const float*)d_in[5];
    const float* w2 = (const float*)d_in[6];
    const float* b2 = (const float*)d_in[7];

    const int B = in_sizes[0] / 64;   // batch rows
    const int T = in_sizes[1];        // number of time points

    cudaFuncSetAttribute(node_kernel,
                         cudaFuncAttributeMaxDynamicSharedMemorySize, SMEM_BYTES);

    node_kernel<<<B / M_TILE, NTHREADS, SMEM_BYTES>>>(
        y0, ts, w0, b0, w1, b1, w2, b2, (float*)d_out, T);
}

// round 9
// speedup vs baseline: 1.0623x; 1.0623x over previous
#include <cuda_runtime.h>

// ---------------------------------------------------------------------------
// NeuralODE Tsit5 — persistent fused kernel, v9 "dual-stream".
// CTA = 16 batch rows, 256 threads (8 warps, 2/SMSP). All weights in SMEM.
// No K-split (full K per warp -> only 4 barriers/stage, no reduce pass).
// Each warp handles cols c0..c0+CT-1 for TWO independent row streams
// (rows r and r+8) in one fused loop: weight loads shared by both streams,
// and the two streams' FFMA2 chains interleave to hide LDS latency.
// ---------------------------------------------------------------------------

#define NTHREADS 256
#define M_TILE   16

__constant__ float d_cs[6] = {0.0f, 0.161f, 0.327f, 0.9f, 0.9800255409045097f, 1.0f};
__constant__ float d_A[6][5] = {
    {0.f, 0.f, 0.f, 0.f, 0.f},
    {0.161f, 0.f, 0.f, 0.f, 0.f},
    {-0.008480655492356989f, 0.335480655492357f, 0.f, 0.f, 0.f},
    {2.8971530571054935f, -6.359448489975075f, 4.3622954328695815f, 0.f, 0.f},
    {5.325864828439257f, -11.748883564062828f, 7.4955393428898365f, -0.09249506636175525f, 0.f},
    {5.86145544294642f, -12.92096931784711f, 8.159367898576159f, -0.071584973281401f, -0.028269050394068383f}
};
__constant__ float d_B[6] = {
    0.09646076681806523f, 0.01f, 0.4798896504144996f,
    1.379008574103742f, -3.290069515436081f, 2.324710524099774f
};

// ---- f32x2 helpers ---------------------------------------------------------
__device__ __forceinline__ unsigned long long pack2(float x, float y) {
    unsigned long long r;
    asm("mov.b64 %0, {%1, %2};" : "=l"(r) : "f"(x), "f"(y));
    return r;
}
__device__ __forceinline__ float2 unpack2(unsigned long long v) {
    float2 f;
    asm("mov.b64 {%0, %1}, %2;" : "=f"(f.x), "=f"(f.y) : "l"(v));
    return f;
}
__device__ __forceinline__ void ffma2(unsigned long long& d,
                                      unsigned long long a,
                                      unsigned long long b) {
    asm("fma.rn.f32x2 %0, %1, %2, %0;" : "+l"(d) : "l"(a), "l"(b));
}

// ---- sizes / strides (floats) ----------------------------------------------
// Act strides: s*4 mod 128 = {16} family -> 8 rows hit disjoint bank regions.
#define KP0 34      // layer0 k-pairs: 68 = t + 64 y + 3 zero pad
#define KP1 64
#define KP2 64
#define SA0 68      // 272 B % 128 = 16
#define SA1 132     // 528 B % 128 = 16
#define SKB 66      // 264 B % 128 = 8
#define KBROW (M_TILE*SKB)

#define U64_WORDS (KP0*128 + KP1*128 + KP2*64)
#define F32_WORDS (128 + 128 + 64 + M_TILE*SA0 + 2*M_TILE*SA1 + 6*KBROW + M_TILE*64)
#define SMEM_BYTES (U64_WORDS*8 + F32_WORDS*4)   // ~186 KB

// ---- dual-stream MLP layer --------------------------------------------------
// Warp owns cols c0..c0+(N/8)-1; lane (r=lane>>2, lc=lane&3) computes rows
// {r, r+8} x CT cols at c0. Weight loads feed both row streams.
template<int N, int CT, int KP, int SIN, int SOUT, bool RELU>
__device__ __forceinline__ void layer_dual(const float* __restrict__ actIn,
                                           const unsigned long long* __restrict__ wp,
                                           const float* __restrict__ bias,
                                           float* __restrict__ outp,
                                           int r, int c0) {
    const unsigned long long* wr = wp + c0;
    const float* aA = actIn + r * SIN;
    const float* aB = aA + 8 * SIN;

    unsigned long long accA[CT], accB[CT];
#pragma unroll
    for (int j = 0; j < CT; j++) { accA[j] = 0ull; accB[j] = 0ull; }

#pragma unroll 4
    for (int kp = 0; kp < KP; kp++) {
        unsigned long long a0 = *reinterpret_cast<const unsigned long long*>(aA + 2 * kp);
        unsigned long long b0 = *reinterpret_cast<const unsigned long long*>(aB + 2 * kp);
        if constexpr (CT == 4) {
            ulonglong2 wx = *reinterpret_cast<const ulonglong2*>(wr + kp * N);
            ulonglong2 wy = *reinterpret_cast<const ulonglong2*>(wr + kp * N + 2);
            ffma2(accA[0], a0, wx.x);
            ffma2(accB[0], b0, wx.x);
            ffma2(accA[1], a0, wx.y);
            ffma2(accB[1], b0, wx.y);
            ffma2(accA[2], a0, wy.x);
            ffma2(accB[2], b0, wy.x);
            ffma2(accA[3], a0, wy.y);
            ffma2(accB[3], b0, wy.y);
        } else {
            ulonglong2 wx = *reinterpret_cast<const ulonglong2*>(wr + kp * N);
            ffma2(accA[0], a0, wx.x);
            ffma2(accB[0], b0, wx.x);
            ffma2(accA[1], a0, wx.y);
            ffma2(accB[1], b0, wx.y);
        }
    }

    // epilogue: horizontal add + bias (+ReLU), vector stores for both streams
    float vA[CT], vB[CT];
#pragma unroll
    for (int j = 0; j < CT; j++) {
        float bv = bias[c0 + j];
        float2 pA = unpack2(accA[j]);
        float2 pB = unpack2(accB[j]);
        vA[j] = pA.x + pA.y + bv;
        vB[j] = pB.x + pB.y + bv;
        if (RELU) { vA[j] = fmaxf(vA[j], 0.f); vB[j] = fmaxf(vB[j], 0.f); }
    }
    float* oA = outp + r * SOUT + c0;
    float* oB = outp + (r + 8) * SOUT + c0;
    if constexpr (CT == 4) {
        *reinterpret_cast<float4*>(oA) = make_float4(vA[0], vA[1], vA[2], vA[3]);
        *reinterpret_cast<float4*>(oB) = make_float4(vB[0], vB[1], vB[2], vB[3]);
    } else {
        *reinterpret_cast<float2*>(oA) = make_float2(vA[0], vA[1]);
        *reinterpret_cast<float2*>(oB) = make_float2(vB[0], vB[1]);
    }
}

// ---------------------------------------------------------------------------
__global__ void __launch_bounds__(NTHREADS, 1)
node_kernel(const float* __restrict__ y0, const float* __restrict__ ts,
            const float* __restrict__ w0, const float* __restrict__ b0,
            const float* __restrict__ w1, const float* __restrict__ b1,
            const float* __restrict__ w2, const float* __restrict__ b2,
            float* __restrict__ out, int T) {
    extern __shared__ unsigned long long smem_u64[];
    unsigned long long* wp0 = smem_u64;
    unsigned long long* wp1 = wp0 + KP0 * 128;
    unsigned long long* wp2 = wp1 + KP1 * 128;
    float* fb   = reinterpret_cast<float*>(wp2 + KP2 * 64);
    float* sb0  = fb;            fb += 128;
    float* sb1  = fb;            fb += 128;
    float* sb2  = fb;            fb += 64;
    float* act0 = fb;            fb += M_TILE * SA0;
    float* act1 = fb;            fb += M_TILE * SA1;
    float* act2 = fb;            fb += M_TILE * SA1;
    float* kbuf = fb;            fb += 6 * KBROW;
    float* ysh  = fb;

    const int tid  = threadIdx.x;
    const int lane = tid & 31;
    const int warp = tid >> 5;
    const int r    = lane >> 2;              // stream rows {r, r+8}
    const int lc   = lane & 3;
    const int row0 = blockIdx.x * M_TILE;

    const int c128 = warp * 16 + lc * 4;     // N=128: lane owns 4 cols
    const int c64  = warp * 8  + lc * 2;     // N=64:  lane owns 2 cols

    // ---- one-time setup: packed transposed weights, biases, y, act0 pad ----
    for (int idx = tid; idx < KP0 * 128; idx += NTHREADS) {
        int kp = idx >> 7, n = idx & 127;
        int k0 = 2 * kp, k1 = 2 * kp + 1;
        float a = (k0 < 65) ? w0[n * 65 + k0] : 0.0f;
        float b = (k1 < 65) ? w0[n * 65 + k1] : 0.0f;
        wp0[idx] = pack2(a, b);
    }
    for (int idx = tid; idx < KP1 * 128; idx += NTHREADS) {
        int kp = idx >> 7, n = idx & 127;
        wp1[idx] = pack2(w1[n * 128 + 2 * kp], w1[n * 128 + 2 * kp + 1]);
    }
    for (int idx = tid; idx < KP2 * 64; idx += NTHREADS) {
        int kp = idx >> 6, n = idx & 63;
        wp2[idx] = pack2(w2[n * 128 + 2 * kp], w2[n * 128 + 2 * kp + 1]);
    }
    for (int idx = tid; idx < 128; idx += NTHREADS) { sb0[idx] = b0[idx]; sb1[idx] = b1[idx]; }
    for (int idx = tid; idx < 64;  idx += NTHREADS) sb2[idx] = b2[idx];
    for (int idx = tid; idx < M_TILE * 64; idx += NTHREADS)
        ysh[idx] = y0[row0 * 64 + idx];
    if (tid < M_TILE) {                      // zero act0 K-pad cols 65..67
        act0[tid * SA0 + 65] = 0.0f;
        act0[tid * SA0 + 66] = 0.0f;
        act0[tid * SA0 + 67] = 0.0f;
    }
    __syncthreads();

    const float dt = ts[1] - ts[0];
    const int steps = T - 1;

    // prologue/epilogue mapping: thread = row pr, 4 consecutive cols at pc
    const int pr = tid >> 4;
    const int pc = (tid & 15) * 4;

    for (int st = 0; st < steps; st++) {
        const float t = ts[st];
        for (int s = 0; s < 6; s++) {
            // ---- prologue: act0 = [t_s, y + dt * sum_j A[s][j] k_j, pad] ----
            if (pc == 0) act0[pr * SA0] = fmaf(d_cs[s], dt, t);
#pragma unroll
            for (int qq = 0; qq < 4; qq++) {
                float acc = 0.0f;
                for (int j = 0; j < s; j++)
                    acc = fmaf(d_A[s][j], kbuf[j * KBROW + pr * SKB + pc + qq], acc);
                act0[pr * SA0 + 1 + pc + qq] = fmaf(dt, acc, ysh[pr * 64 + pc + qq]);
            }
            __syncthreads();

            layer_dual<128, 4, KP0, SA0, SA1, true >(act0, wp0, sb0, act1, r, c128);
            __syncthreads();
            layer_dual<128, 4, KP1, SA1, SA1, true >(act1, wp1, sb1, act2, r, c128);
            __syncthreads();
            layer_dual<64,  2, KP2, SA1, SKB, false>(act2, wp2, sb2,
                                                     kbuf + s * KBROW, r, c64);
            __syncthreads();
        }
        // ---- y += dt * sum_j B[j] k_j ----
#pragma unroll
        for (int qq = 0; qq < 4; qq++) {
            const int kc = pr * SKB + pc + qq;
            float acc = d_B[0] * kbuf[kc];
#pragma unroll
            for (int j = 1; j < 6; j++)
                acc = fmaf(d_B[j], kbuf[j * KBROW + kc], acc);
            ysh[pr * 64 + pc + qq] = fmaf(dt, acc, ysh[pr * 64 + pc + qq]);
        }
        __syncthreads();
    }

    for (int idx = tid; idx < M_TILE * 64; idx += NTHREADS)
        out[row0 * 64 + idx] = ysh[idx];
}

// ---------------------------------------------------------------------------
extern "C" void kernel_launch(void* const* d_in, const int* in_sizes, int n_in,
                              void* d_out, int out_size) {
    const float* y0 = (const float*)d_in[0];
    const float* ts = (const float*)d_in[1];
    const float* w0 = (const float*)d_in[2];
    const float* b0 = (const float*)d_in[3];
    const float* w1 = (const float*)d_in[4];
    const float* b1 = (const float*)d_in[5];
    const float* w2 = (const float*)d_in[6];
    const float* b2 = (const float*)d_in[7];

    const int B = in_sizes[0] / 64;   // batch rows
    const int T = in_sizes[1];        // number of time points

    cudaFuncSetAttribute(node_kernel,
                         cudaFuncAttributeMaxDynamicSharedMemorySize, SMEM_BYTES);

    node_kernel<<<B / M_TILE, NTHREADS, SMEM_BYTES>>>(
        y0, ts, w0, b0, w1, b1, w2, b2, (float*)d_out, T);
}

// round 10
// speedup vs baseline: 1.0861x; 1.0224x over previous
#include <cuda_runtime.h>

// ---------------------------------------------------------------------------
// NeuralODE Tsit5 — persistent fused kernel, v10.
// 4 warps / 128 threads / CTA, 16 batch rows, all weights in SMEM.
// Warp q streams K-quarter q over the FULL 16x128 tile, lane tile 8x8
// (2 bytes requested per f32x2 FMA). Partials stored lane-major via STS.128.
// 6 __syncthreads per stage; prologue + y-update fused into per-warp-owned
// column windows (warp q owns act0 cols [20q,20q+20) = its stream-0 K-slice).
// ---------------------------------------------------------------------------

#define NTHREADS 128
#define M_TILE   16

__constant__ float d_cs[6] = {0.0f, 0.161f, 0.327f, 0.9f, 0.9800255409045097f, 1.0f};
__constant__ float d_A[6][5] = {
    {0.f, 0.f, 0.f, 0.f, 0.f},
    {0.161f, 0.f, 0.f, 0.f, 0.f},
    {-0.008480655492356989f, 0.335480655492357f, 0.f, 0.f, 0.f},
    {2.8971530571054935f, -6.359448489975075f, 4.3622954328695815f, 0.f, 0.f},
    {5.325864828439257f, -11.748883564062828f, 7.4955393428898365f, -0.09249506636175525f, 0.f},
    {5.86145544294642f, -12.92096931784711f, 8.159367898576159f, -0.071584973281401f, -0.028269050394068383f}
};
__constant__ float d_B[6] = {
    0.09646076681806523f, 0.01f, 0.4798896504144996f,
    1.379008574103742f, -3.290069515436081f, 2.324710524099774f
};

typedef unsigned long long u64;

__device__ __forceinline__ u64 pack2(float x, float y) {
    u64 r; asm("mov.b64 %0, {%1, %2};" : "=l"(r) : "f"(x), "f"(y)); return r;
}
__device__ __forceinline__ float hadd2(u64 v) {
    float2 f; asm("mov.b64 {%0, %1}, %2;" : "=f"(f.x), "=f"(f.y) : "l"(v));
    return f.x + f.y;
}
__device__ __forceinline__ void ffma2(u64& d, u64 a, u64 b) {
    asm("fma.rn.f32x2 %0, %1, %2, %0;" : "+l"(d) : "l"(a), "l"(b));
}

// ---- sizes (floats unless noted) -------------------------------------------
#define KP0 40          // layer0 k-pairs (80 = t + 64 y + 15 pad), KPW0=10
#define KPW0 10
#define KP1 64
#define KPW1 16
#define KP2 64
#define KPW2 16
#define SA0 84
#define SA1 132
#define SKB 68
#define KBSTG (M_TILE*SKB)
#define PL 68           // lane-major partial stride (64 vals + 4 pad)
#define PSLOT (32*PL)   // floats per K-quarter slot

// weight entries (ulonglong2, 16B each): per kp, N=128 -> 64 entries, N=64 -> 32
#define WE0 (KP0*64)
#define WE1 (KP1*64)
#define WE2 (KP2*32)
#define F32_WORDS (128+128+64 + M_TILE*SA0 + M_TILE*SA1 + 6*KBSTG + M_TILE*64 + 4*PSLOT)
#define SMEM_BYTES ((WE0+WE1+WE2)*16 + F32_WORDS*4)   // 219,392 B

// ---- stream: warp's K-quarter over full 16xN tile, 8x8 lane tile -----------
// aBase: act + rowg*8*SIN + 2*kq*KPW (16B-aligned). wBase: wq + kq*KPW*8*CT + colg.
// pb: slot_kq + lane*PL. Weight entry (kp,m) at [kp*8*CT + m*16] holds cols
// (colg+32m, colg+32m+16) as two packed k-pair u64s.
template<int CT, int KPW, int SIN>
__device__ __forceinline__ void stream_tile(const float* __restrict__ aBase,
                                            const ulonglong2* __restrict__ wBase,
                                            float* __restrict__ pb) {
    u64 acc[8][CT];
#pragma unroll
    for (int i = 0; i < 8; i++)
#pragma unroll
        for (int j = 0; j < CT; j++) acc[i][j] = 0ull;

#pragma unroll 2
    for (int kp = 0; kp < KPW; kp++) {
        u64 a[8];
#pragma unroll
        for (int i = 0; i < 8; i++)
            a[i] = *reinterpret_cast<const u64*>(aBase + i * SIN + 2 * kp);
#pragma unroll
        for (int m = 0; m < CT / 2; m++) {
            ulonglong2 w = wBase[kp * 8 * CT + m * 16];
#pragma unroll
            for (int i = 0; i < 8; i++) {
                ffma2(acc[i][2 * m],     a[i], w.x);
                ffma2(acc[i][2 * m + 1], a[i], w.y);
            }
        }
    }
    // hadd + lane-major vector store: value idx = i*CT + j
#pragma unroll
    for (int i = 0; i < 8; i++)
#pragma unroll
        for (int j4 = 0; j4 < CT / 4; j4++) {
            float4 v = make_float4(hadd2(acc[i][4*j4]),   hadd2(acc[i][4*j4+1]),
                                   hadd2(acc[i][4*j4+2]), hadd2(acc[i][4*j4+3]));
            *reinterpret_cast<float4*>(pb + i * CT + 4 * j4) = v;
        }
}

// ---- reduce 4 lane-major slots -> dst[16 x N] (+bias, optional ReLU) -------
// Thread (w = tid>>5, l = tid&31): handles stream-lane l's rows i in {2w,2w+1}.
// Lane l maps to (rowg = l>>4, colg = l&15); value (i,j) -> out(rowg*8+i, colg+16j).
template<int CT, int SOUT, bool RELU>
__device__ __forceinline__ void reduce_pass(const float* __restrict__ pbuf,
                                            const float* __restrict__ bias,
                                            float* __restrict__ dst,
                                            int w, int l) {
    const int rowg = l >> 4, colg = l & 15;
    float bv[CT];
#pragma unroll
    for (int j = 0; j < CT; j++) bv[j] = bias[colg + 16 * j];
#pragma unroll
    for (int ii = 0; ii < 2; ii++) {
        const int i = 2 * w + ii;
        float s[CT];
#pragma unroll
        for (int j = 0; j < CT; j++) s[j] = bv[j];
#pragma unroll
        for (int b = 0; b < 4; b++) {
            const float* p = pbuf + b * PSLOT + l * PL + i * CT;
#pragma unroll
            for (int j4 = 0; j4 < CT / 4; j4++) {
                float4 t = *reinterpret_cast<const float4*>(p + 4 * j4);
                s[4*j4] += t.x; s[4*j4+1] += t.y; s[4*j4+2] += t.z; s[4*j4+3] += t.w;
            }
        }
        float* o = dst + (rowg * 8 + i) * SOUT + colg;
#pragma unroll
        for (int j = 0; j < CT; j++) {
            float v = s[j];
            if (RELU) v = fmaxf(v, 0.0f);
            o[16 * j] = v;
        }
    }
}

// ---------------------------------------------------------------------------
__global__ void __launch_bounds__(NTHREADS, 1)
node_kernel(const float* __restrict__ y0, const float* __restrict__ ts,
            const float* __restrict__ w0, const float* __restrict__ b0,
            const float* __restrict__ w1, const float* __restrict__ b1,
            const float* __restrict__ w2, const float* __restrict__ b2,
            float* __restrict__ out, int T) {
    extern __shared__ ulonglong2 smem_w[];
    ulonglong2* wq0 = smem_w;
    ulonglong2* wq1 = wq0 + WE0;
    ulonglong2* wq2 = wq1 + WE1;
    float* fb   = reinterpret_cast<float*>(wq2 + WE2);
    float* sb0  = fb;  fb += 128;
    float* sb1  = fb;  fb += 128;
    float* sb2  = fb;  fb += 64;
    float* act0 = fb;  fb += M_TILE * SA0;
    float* act1 = fb;  fb += M_TILE * SA1;   // also serves as act2 (aliased)
    float* kbuf = fb;  fb += 6 * KBSTG;
    float* ysh  = fb;  fb += M_TILE * 64;
    float* pbuf = fb;

    const int tid  = threadIdx.x;
    const int lane = tid & 31;
    const int warp = tid >> 5;               // = K-quarter q
    const int rowg = lane >> 4;
    const int colg = lane & 15;
    const int row0 = blockIdx.x * M_TILE;

    // ---- setup: packed col-pair weights -------------------------------------
    // N=128 entry e: kp=e>>6, m=(e>>4)&3, cg=e&15; cols c=cg+32m, c+16.
    for (int e = tid; e < WE0; e += NTHREADS) {
        int kp = e >> 6, m = (e >> 4) & 3, cg = e & 15;
        int c = cg + 32 * m;
        int k0 = 2 * kp, k1 = 2 * kp + 1;
        float a0 = (k0 < 65) ? w0[c * 65 + k0] : 0.0f;
        float a1 = (k1 < 65) ? w0[c * 65 + k1] : 0.0f;
        float b0v = (k0 < 65) ? w0[(c + 16) * 65 + k0] : 0.0f;
        float b1v = (k1 < 65) ? w0[(c + 16) * 65 + k1] : 0.0f;
        ulonglong2 v; v.x = pack2(a0, a1); v.y = pack2(b0v, b1v);
        wq0[e] = v;
    }
    for (int e = tid; e < WE1; e += NTHREADS) {
        int kp = e >> 6, m = (e >> 4) & 3, cg = e & 15;
        int c = cg + 32 * m;
        ulonglong2 v;
        v.x = pack2(w1[c * 128 + 2 * kp], w1[c * 128 + 2 * kp + 1]);
        v.y = pack2(w1[(c + 16) * 128 + 2 * kp], w1[(c + 16) * 128 + 2 * kp + 1]);
        wq1[e] = v;
    }
    // N=64 entry e: kp=e>>5, m=(e>>4)&1, cg=e&15.
    for (int e = tid; e < WE2; e += NTHREADS) {
        int kp = e >> 5, m = (e >> 4) & 1, cg = e & 15;
        int c = cg + 32 * m;
        ulonglong2 v;
        v.x = pack2(w2[c * 128 + 2 * kp], w2[c * 128 + 2 * kp + 1]);
        v.y = pack2(w2[(c + 16) * 128 + 2 * kp], w2[(c + 16) * 128 + 2 * kp + 1]);
        wq2[e] = v;
    }
    for (int i = tid; i < 128; i += NTHREADS) { sb0[i] = b0[i]; sb1[i] = b1[i]; }
    for (int i = tid; i < 64;  i += NTHREADS) sb2[i] = b2[i];
    for (int i = tid; i < M_TILE * 64; i += NTHREADS)
        ysh[i] = y0[row0 * 64 + i];
    if (tid < M_TILE) {                       // zero act0 pad cols 65..79
#pragma unroll
        for (int c = 65; c < 80; c++) act0[tid * SA0 + c] = 0.0f;
    }
    __syncthreads();

    const float dt = ts[1] - ts[0];
    const int steps = T - 1;

    // lane-fixed stream pointers
    float* pbW = pbuf + warp * PSLOT + lane * PL;
    const ulonglong2* w0W = wq0 + (warp * KPW0) * 64 + colg;
    const ulonglong2* w1W = wq1 + (warp * KPW1) * 64 + colg;
    const ulonglong2* w2W = wq2 + (warp * KPW2) * 32 + colg;
    const float* a0W = act0 + rowg * 8 * SA0 + 2 * (warp * KPW0);
    const float* a1W = act1 + rowg * 8 * SA1 + 2 * (warp * KPW1);
    const float* a2W = act1 + rowg * 8 * SA1 + 2 * (warp * KPW2);  // act2 == act1

    // prologue mapping: warp q owns act0 cols [20q, 20q+20), its stream-0 slice.
    // lane: row = lane>>1, 10 cols at cb = 20q + (lane&1)*10.
    const int prow = lane >> 1;
    const int cb   = warp * 20 + (lane & 1) * 10;
    const float* kbRow = kbuf + prow * SKB;
    const float* yRow  = ysh + prow * 64;

    for (int st = 0; st < steps; st++) {
        const float t = ts[st];
        for (int s = 0; s < 6; s++) {
            // ---- fused prologue (warp-local window; no barrier needed) ------
            const float ts_ = fmaf(d_cs[s], dt, t);
#pragma unroll
            for (int cc = 0; cc < 10; cc++) {
                const int ac = cb + cc;
                if (ac == 0) { act0[prow * SA0] = ts_; continue; }
                const int yc = ac - 1;
                if (yc >= 64) break;
                float yv = yRow[yc];
                if (s == 0) {
                    if (st > 0) {   // fused Tsit5 y-update from previous step
                        float acc = d_B[0] * kbRow[yc];
#pragma unroll
                        for (int j = 1; j < 6; j++)
                            acc = fmaf(d_B[j], kbRow[j * KBSTG + yc], acc);
                        yv = fmaf(dt, acc, yv);
                        ysh[prow * 64 + yc] = yv;
                    }
                    act0[prow * SA0 + ac] = yv;
                } else {
                    float acc = d_A[s][0] * kbRow[yc];
                    for (int j = 1; j < s; j++)
                        acc = fmaf(d_A[s][j], kbRow[j * KBSTG + yc], acc);
                    act0[prow * SA0 + ac] = fmaf(dt, acc, yv);
                }
            }
            __syncwarp();

            stream_tile<8, KPW0, SA0>(a0W, w0W, pbW);
            __syncthreads();
            reduce_pass<8, SA1, true>(pbuf, sb0, act1, warp, lane);
            __syncthreads();

            stream_tile<8, KPW1, SA1>(a1W, w1W, pbW);
            __syncthreads();
            reduce_pass<8, SA1, true>(pbuf, sb1, act1, warp, lane);
            __syncthreads();

            stream_tile<4, KPW2, SA1>(a2W, w2W, pbW);
            __syncthreads();
            reduce_pass<4, SKB, false>(pbuf, sb2, kbuf + s * KBSTG, warp, lane);
            __syncthreads();
        }
    }

    // ---- final y-update (fused form of the last step's epilogue) -----------
#pragma unroll
    for (int cc = 0; cc < 10; cc++) {
        const int ac = cb + cc;
        if (ac == 0) continue;
        const int yc = ac - 1;
        if (yc >= 64) break;
        float acc = d_B[0] * kbRow[yc];
#pragma unroll
        for (int j = 1; j < 6; j++)
            acc = fmaf(d_B[j], kbRow[j * KBSTG + yc], acc);
        out[(row0 + prow) * 64 + yc] = fmaf(dt, acc, yRow[yc]);
    }
}

// ---------------------------------------------------------------------------
extern "C" void kernel_launch(void* const* d_in, const int* in_sizes, int n_in,
                              void* d_out, int out_size) {
    const float* y0 = (const float*)d_in[0];
    const float* ts = (const float*)d_in[1];
    const float* w0 = (const float*)d_in[2];
    const float* b0 = (const float*)d_in[3];
    const float* w1 = (const float*)d_in[4];
    const float* b1 = (const float*)d_in[5];
    const float* w2 = (const float*)d_in[6];
    const float* b2 = (const float*)d_in[7];

    const int B = in_sizes[0] / 64;   // batch rows
    const int T = in_sizes[1];        // number of time points

    cudaFuncSetAttribute(node_kernel,
                         cudaFuncAttributeMaxDynamicSharedMemorySize, SMEM_BYTES);

    node_kernel<<<B / M_TILE, NTHREADS, SMEM_BYTES>>>(
        y0, ts, w0, b0, w1, b1, w2, b2, (float*)d_out, T);
}

// round 11
// speedup vs baseline: 1.2217x; 1.1249x over previous
#include <cuda_runtime.h>

// ---------------------------------------------------------------------------
// NeuralODE Tsit5 — persistent fused kernel, v11 = v7 occupancy x v10 engine.
// 8 warps / 256 threads / CTA (2 warps per SMSP), 16 batch rows.
// Warp (q,h): streams K-quarter q over rows [8h,8h+8) x N, lane tile 4x8.
// Packed ulonglong2 weight col-pairs, lane-major float4 partials,
// 6 __syncthreads per stage, warp-local prologue + fused Tsit5 y-update.
// ---------------------------------------------------------------------------

#define NTHREADS 256
#define M_TILE   16

__constant__ float d_cs[6] = {0.0f, 0.161f, 0.327f, 0.9f, 0.9800255409045097f, 1.0f};
__constant__ float d_A[6][5] = {
    {0.f, 0.f, 0.f, 0.f, 0.f},
    {0.161f, 0.f, 0.f, 0.f, 0.f},
    {-0.008480655492356989f, 0.335480655492357f, 0.f, 0.f, 0.f},
    {2.8971530571054935f, -6.359448489975075f, 4.3622954328695815f, 0.f, 0.f},
    {5.325864828439257f, -11.748883564062828f, 7.4955393428898365f, -0.09249506636175525f, 0.f},
    {5.86145544294642f, -12.92096931784711f, 8.159367898576159f, -0.071584973281401f, -0.028269050394068383f}
};
__constant__ float d_B[6] = {
    0.09646076681806523f, 0.01f, 0.4798896504144996f,
    1.379008574103742f, -3.290069515436081f, 2.324710524099774f
};

typedef unsigned long long u64;

__device__ __forceinline__ u64 pack2(float x, float y) {
    u64 r; asm("mov.b64 %0, {%1, %2};" : "=l"(r) : "f"(x), "f"(y)); return r;
}
__device__ __forceinline__ float hadd2(u64 v) {
    float2 f; asm("mov.b64 {%0, %1}, %2;" : "=f"(f.x), "=f"(f.y) : "l"(v));
    return f.x + f.y;
}
__device__ __forceinline__ void ffma2(u64& d, u64 a, u64 b) {
    asm("fma.rn.f32x2 %0, %1, %2, %0;" : "+l"(d) : "l"(a), "l"(b));
}

// ---- sizes (floats unless noted) -------------------------------------------
#define KP0 40          // layer0 k-pairs (80 = t + 64 y + 15 pad)
#define KPW0 10
#define KP1 64
#define KPW1 16
#define KP2 64
#define KPW2 16
#define SA0 84
#define SA1 132
#define SKB 68
#define KBSTG (M_TILE*SKB)
#define PL 36           // lane-major partial stride (32 vals + 4 pad)
#define HOFF (32*PL)    // per row-half offset inside a slot
#define PSLOT (2*HOFF)  // floats per K-quarter slot

// weight entries (ulonglong2): per kp, N=128 -> 64 entries, N=64 -> 32
#define WE0 (KP0*64)
#define WE1 (KP1*64)
#define WE2 (KP2*32)
#define F32_WORDS (128+128+64 + M_TILE*SA0 + M_TILE*SA1 + 6*KBSTG + M_TILE*64 + 4*PSLOT)
#define SMEM_BYTES ((WE0+WE1+WE2)*16 + F32_WORDS*4)   // ~221 KB

// ---- stream: warp's K-quarter, 8-row half, lane tile 4x8 -------------------
// aBase = act + rowbase*SIN + 2*q*KPW; wBase = wq + q*KPW*(8*CT) + colg;
// pb = pbuf + q*PSLOT + h*HOFF + lane*PL.
template<int CT, int KPW, int SIN>
__device__ __forceinline__ void stream_tile(const float* __restrict__ aBase,
                                            const ulonglong2* __restrict__ wBase,
                                            float* __restrict__ pb) {
    u64 acc[4][CT];
#pragma unroll
    for (int i = 0; i < 4; i++)
#pragma unroll
        for (int j = 0; j < CT; j++) acc[i][j] = 0ull;

#pragma unroll 2
    for (int kp = 0; kp < KPW; kp++) {
        u64 a[4];
#pragma unroll
        for (int i = 0; i < 4; i++)
            a[i] = *reinterpret_cast<const u64*>(aBase + i * SIN + 2 * kp);
#pragma unroll
        for (int m = 0; m < CT / 2; m++) {
            ulonglong2 w = wBase[kp * (8 * CT) + m * 16];
#pragma unroll
            for (int i = 0; i < 4; i++) {
                ffma2(acc[i][2 * m],     a[i], w.x);
                ffma2(acc[i][2 * m + 1], a[i], w.y);
            }
        }
    }
    // hadd + lane-major float4 stores: value idx = i*CT + j
#pragma unroll
    for (int i = 0; i < 4; i++)
#pragma unroll
        for (int j4 = 0; j4 < CT / 4; j4++) {
            float4 v = make_float4(hadd2(acc[i][4*j4]),   hadd2(acc[i][4*j4+1]),
                                   hadd2(acc[i][4*j4+2]), hadd2(acc[i][4*j4+3]));
            *reinterpret_cast<float4*>(pb + i * CT + 4 * j4) = v;
        }
}

// ---- reduce 4 K-quarter slots -> dst[16 x N] (+bias, optional ReLU) --------
// Thread (w = tid>>5, l = tid&31): w = (h'=w>>2, i'=w&3); lane l = (rowg, colg).
// Handles row 8h' + 4rowg + i', cols colg + 16j.
template<int CT, int SOUT, bool RELU>
__device__ __forceinline__ void reduce_pass(const float* __restrict__ pbuf,
                                            const float* __restrict__ bias,
                                            float* __restrict__ dst,
                                            int w, int l) {
    const int hp = w >> 2, ip = w & 3;
    const int rowg = l >> 4, colg = l & 15;
    const int row = 8 * hp + 4 * rowg + ip;

    float s[CT];
#pragma unroll
    for (int j = 0; j < CT; j++) s[j] = bias[colg + 16 * j];
#pragma unroll
    for (int b = 0; b < 4; b++) {
        const float* p = pbuf + b * PSLOT + hp * HOFF + l * PL + ip * CT;
#pragma unroll
        for (int j4 = 0; j4 < CT / 4; j4++) {
            float4 t = *reinterpret_cast<const float4*>(p + 4 * j4);
            s[4*j4] += t.x; s[4*j4+1] += t.y; s[4*j4+2] += t.z; s[4*j4+3] += t.w;
        }
    }
    float* o = dst + row * SOUT + colg;
#pragma unroll
    for (int j = 0; j < CT; j++) {
        float v = s[j];
        if (RELU) v = fmaxf(v, 0.0f);
        o[16 * j] = v;
    }
}

// ---------------------------------------------------------------------------
__global__ void __launch_bounds__(NTHREADS, 1)
node_kernel(const float* __restrict__ y0, const float* __restrict__ ts,
            const float* __restrict__ w0, const float* __restrict__ b0,
            const float* __restrict__ w1, const float* __restrict__ b1,
            const float* __restrict__ w2, const float* __restrict__ b2,
            float* __restrict__ out, int T) {
    extern __shared__ ulonglong2 smem_w[];
    ulonglong2* wq0 = smem_w;
    ulonglong2* wq1 = wq0 + WE0;
    ulonglong2* wq2 = wq1 + WE1;
    float* fb   = reinterpret_cast<float*>(wq2 + WE2);
    float* sb0  = fb;  fb += 128;
    float* sb1  = fb;  fb += 128;
    float* sb2  = fb;  fb += 64;
    float* act0 = fb;  fb += M_TILE * SA0;
    float* act1 = fb;  fb += M_TILE * SA1;   // also serves as act2 (aliased)
    float* kbuf = fb;  fb += 6 * KBSTG;
    float* ysh  = fb;  fb += M_TILE * 64;
    float* pbuf = fb;

    const int tid  = threadIdx.x;
    const int lane = tid & 31;
    const int warp = tid >> 5;
    const int q    = warp >> 1;              // K quarter
    const int h    = warp & 1;               // row half
    const int rowg = lane >> 4;
    const int colg = lane & 15;
    const int rowbase = 8 * h + 4 * rowg;
    const int row0 = blockIdx.x * M_TILE;

    // ---- setup: packed col-pair weights (v10 layout) ------------------------
    for (int e = tid; e < WE0; e += NTHREADS) {
        int kp = e >> 6, m = (e >> 4) & 3, cg = e & 15;
        int c = cg + 32 * m;
        int k0 = 2 * kp, k1 = 2 * kp + 1;
        float a0 = (k0 < 65) ? w0[c * 65 + k0] : 0.0f;
        float a1 = (k1 < 65) ? w0[c * 65 + k1] : 0.0f;
        float c0v = (k0 < 65) ? w0[(c + 16) * 65 + k0] : 0.0f;
        float c1v = (k1 < 65) ? w0[(c + 16) * 65 + k1] : 0.0f;
        ulonglong2 v; v.x = pack2(a0, a1); v.y = pack2(c0v, c1v);
        wq0[e] = v;
    }
    for (int e = tid; e < WE1; e += NTHREADS) {
        int kp = e >> 6, m = (e >> 4) & 3, cg = e & 15;
        int c = cg + 32 * m;
        ulonglong2 v;
        v.x = pack2(w1[c * 128 + 2 * kp], w1[c * 128 + 2 * kp + 1]);
        v.y = pack2(w1[(c + 16) * 128 + 2 * kp], w1[(c + 16) * 128 + 2 * kp + 1]);
        wq1[e] = v;
    }
    for (int e = tid; e < WE2; e += NTHREADS) {
        int kp = e >> 5, m = (e >> 4) & 1, cg = e & 15;
        int c = cg + 32 * m;
        ulonglong2 v;
        v.x = pack2(w2[c * 128 + 2 * kp], w2[c * 128 + 2 * kp + 1]);
        v.y = pack2(w2[(c + 16) * 128 + 2 * kp], w2[(c + 16) * 128 + 2 * kp + 1]);
        wq2[e] = v;
    }
    for (int i = tid; i < 128; i += NTHREADS) { sb0[i] = b0[i]; sb1[i] = b1[i]; }
    for (int i = tid; i < 64;  i += NTHREADS) sb2[i] = b2[i];
    for (int i = tid; i < M_TILE * 64; i += NTHREADS)
        ysh[i] = y0[row0 * 64 + i];
    if (tid < M_TILE) {                       // zero act0 pad cols 65..79
#pragma unroll
        for (int c = 65; c < 80; c++) act0[tid * SA0 + c] = 0.0f;
    }
    __syncthreads();

    const float dt = ts[1] - ts[0];
    const int steps = T - 1;

    // lane-fixed stream pointers
    float* pbW = pbuf + q * PSLOT + h * HOFF + lane * PL;
    const ulonglong2* w0W = wq0 + (q * KPW0) * 64 + colg;
    const ulonglong2* w1W = wq1 + (q * KPW1) * 64 + colg;
    const ulonglong2* w2W = wq2 + (q * KPW2) * 32 + colg;
    const float* a0W = act0 + rowbase * SA0 + 2 * (q * KPW0);
    const float* a1W = act1 + rowbase * SA1 + 2 * (q * KPW1);
    const float* a2W = act1 + rowbase * SA1 + 2 * (q * KPW2);   // act2 == act1

    // warp-local prologue window: rows [8h, 8h+8), act0 cols [20q, 20q+20)
    const int prow = 8 * h + (lane >> 2);
    const int cb   = 20 * q + (lane & 3) * 5;
    const float* kbRow = kbuf + prow * SKB;
    float* yRow = ysh + prow * 64;

    for (int st = 0; st < steps; st++) {
        const float t = ts[st];
        for (int s = 0; s < 6; s++) {
            // ---- warp-local prologue (+ fused Tsit5 y-update at s==0) ------
            const float ts_ = fmaf(d_cs[s], dt, t);
#pragma unroll
            for (int cc = 0; cc < 5; cc++) {
                const int ac = cb + cc;
                if (ac == 0) { act0[prow * SA0] = ts_; continue; }
                const int yc = ac - 1;
                if (yc >= 64) break;
                float yv = yRow[yc];
                if (s == 0) {
                    if (st > 0) {
                        float acc = d_B[0] * kbRow[yc];
#pragma unroll
                        for (int j = 1; j < 6; j++)
                            acc = fmaf(d_B[j], kbRow[j * KBSTG + yc], acc);
                        yv = fmaf(dt, acc, yv);
                        yRow[yc] = yv;
                    }
                    act0[prow * SA0 + ac] = yv;
                } else {
                    float acc = d_A[s][0] * kbRow[yc];
                    for (int j = 1; j < s; j++)
                        acc = fmaf(d_A[s][j], kbRow[j * KBSTG + yc], acc);
                    act0[prow * SA0 + ac] = fmaf(dt, acc, yv);
                }
            }
            __syncwarp();

            stream_tile<8, KPW0, SA0>(a0W, w0W, pbW);
            __syncthreads();
            reduce_pass<8, SA1, true>(pbuf, sb0, act1, warp, lane);
            __syncthreads();

            stream_tile<8, KPW1, SA1>(a1W, w1W, pbW);
            __syncthreads();
            reduce_pass<8, SA1, true>(pbuf, sb1, act1, warp, lane);
            __syncthreads();

            stream_tile<4, KPW2, SA1>(a2W, w2W, pbW);
            __syncthreads();
            reduce_pass<4, SKB, false>(pbuf, sb2, kbuf + s * KBSTG, warp, lane);
            __syncthreads();
        }
    }

    // ---- final fused y-update -> out ----------------------------------------
#pragma unroll
    for (int cc = 0; cc < 5; cc++) {
        const int ac = cb + cc;
        if (ac == 0) continue;
        const int yc = ac - 1;
        if (yc >= 64) break;
        float acc = d_B[0] * kbRow[yc];
#pragma unroll
        for (int j = 1; j < 6; j++)
            acc = fmaf(d_B[j], kbRow[j * KBSTG + yc], acc);
        out[(row0 + prow) * 64 + yc] = fmaf(dt, acc, yRow[yc]);
    }
}

// ---------------------------------------------------------------------------
extern "C" void kernel_launch(void* const* d_in, const int* in_sizes, int n_in,
                              void* d_out, int out_size) {
    const float* y0 = (const float*)d_in[0];
    const float* ts = (const float*)d_in[1];
    const float* w0 = (const float*)d_in[2];
    const float* b0 = (const float*)d_in[3];
    const float* w1 = (const float*)d_in[4];
    const float* b1 = (const float*)d_in[5];
    const float* w2 = (const float*)d_in[6];
    const float* b2 = (const float*)d_in[7];

    const int B = in_sizes[0] / 64;   // batch rows
    const int T = in_sizes[1];        // number of time points

    cudaFuncSetAttribute(node_kernel,
                         cudaFuncAttributeMaxDynamicSharedMemorySize, SMEM_BYTES);

    node_kernel<<<B / M_TILE, NTHREADS, SMEM_BYTES>>>(
        y0, ts, w0, b0, w1, b1, w2, b2, (float*)d_out, T);
}

// round 12
// speedup vs baseline: 1.2409x; 1.0157x over previous
#include <cuda_runtime.h>

// ---------------------------------------------------------------------------
// NeuralODE Tsit5 — persistent fused kernel, v12.
// 16 warps / 512 threads / CTA (4 per SMSP), 16 batch rows, weights in SMEM.
// Warp (q,h,ch): K-quarter q, rows [8h,8h+8), cols [64ch,64ch+64).
// Lane tile 4 rows x 4 cols (16 u64 accs). LDS.128 act loads (2 k-pairs),
// packed ulonglong2 weight col-pairs, lane-major float4 partials (PL=20),
// 6 CTA barriers + 1 paired named barrier per stage, warp-local prologue
// with fused Tsit5 y-update.
// ---------------------------------------------------------------------------

#define NTHREADS 512
#define M_TILE   16

__constant__ float d_cs[6] = {0.0f, 0.161f, 0.327f, 0.9f, 0.9800255409045097f, 1.0f};
__constant__ float d_A[6][5] = {
    {0.f, 0.f, 0.f, 0.f, 0.f},
    {0.161f, 0.f, 0.f, 0.f, 0.f},
    {-0.008480655492356989f, 0.335480655492357f, 0.f, 0.f, 0.f},
    {2.8971530571054935f, -6.359448489975075f, 4.3622954328695815f, 0.f, 0.f},
    {5.325864828439257f, -11.748883564062828f, 7.4955393428898365f, -0.09249506636175525f, 0.f},
    {5.86145544294642f, -12.92096931784711f, 8.159367898576159f, -0.071584973281401f, -0.028269050394068383f}
};
__constant__ float d_B[6] = {
    0.09646076681806523f, 0.01f, 0.4798896504144996f,
    1.379008574103742f, -3.290069515436081f, 2.324710524099774f
};

typedef unsigned long long u64;

__device__ __forceinline__ u64 pack2(float x, float y) {
    u64 r; asm("mov.b64 %0, {%1, %2};" : "=l"(r) : "f"(x), "f"(y)); return r;
}
__device__ __forceinline__ float hadd2(u64 v) {
    float2 f; asm("mov.b64 {%0, %1}, %2;" : "=f"(f.x), "=f"(f.y) : "l"(v));
    return f.x + f.y;
}
__device__ __forceinline__ void ffma2(u64& d, u64 a, u64 b) {
    asm("fma.rn.f32x2 %0, %1, %2, %0;" : "+l"(d) : "l"(a), "l"(b));
}

// ---- sizes (floats unless noted) -------------------------------------------
#define KP0 40          // layer0 k-pairs (80 = t + 64 y + 15 pad)
#define KPW0 10
#define KP1 64
#define KPW1 16
#define KP2 64
#define KPW2 16
#define SA0 84
#define SA1 132
#define SKB 68
#define KBSTG (M_TILE*SKB)
#define PL 20                 // lane partial stride (16 vals + 4 pad; 80B CF)
#define SUB (32*PL)           // per (h,ch) sub-block in a slot
#define PSLOT (4*SUB)         // per K-quarter slot

// weight entries (ulonglong2): per kp, N=128 -> 64 entries, N=64 -> 32
#define WE0 (KP0*64)
#define WE1 (KP1*64)
#define WE2 (KP2*32)
#define F32_WORDS (128+128+64 + M_TILE*SA0 + M_TILE*SA1 + 6*KBSTG + M_TILE*64 + 4*PSLOT)
#define SMEM_BYTES ((WE0+WE1+WE2)*16 + F32_WORDS*4)   // ~220 KB

// ---- stream: warp (q,h,ch), lane tile 4 rows x CT cols ----------------------
// aBase = act + (8h+4rowg)*SIN + 2*q*KPW ; wBase = wq + q*KPW*NENT + ch*(CT*8) + colg
// pb = pbuf + q*PSLOT + (2h+ch)*SUB + lane*PL
template<int CT, int KPW, int SIN, int NENT>
__device__ __forceinline__ void stream_tile(const float* __restrict__ aBase,
                                            const ulonglong2* __restrict__ wBase,
                                            float* __restrict__ pb) {
    u64 acc[4][CT];
#pragma unroll
    for (int i = 0; i < 4; i++)
#pragma unroll
        for (int j = 0; j < CT; j++) acc[i][j] = 0ull;

#pragma unroll 2
    for (int kp2 = 0; kp2 < KPW / 2; kp2++) {
        ulonglong2 av[4];
#pragma unroll
        for (int i = 0; i < 4; i++)
            av[i] = *reinterpret_cast<const ulonglong2*>(aBase + i * SIN + 4 * kp2);
#pragma unroll
        for (int kk = 0; kk < 2; kk++) {
            const int kp = 2 * kp2 + kk;
            u64 wv[CT];
            if constexpr (CT == 4) {
                ulonglong2 wA = wBase[kp * NENT];
                ulonglong2 wB = wBase[kp * NENT + 16];
                wv[0] = wA.x; wv[1] = wA.y; wv[2] = wB.x; wv[3] = wB.y;
            } else {
                ulonglong2 wA = wBase[kp * NENT];
                wv[0] = wA.x; wv[1] = wA.y;
            }
#pragma unroll
            for (int j = 0; j < CT; j++)
#pragma unroll
                for (int i = 0; i < 4; i++) {
                    u64 a = kk ? av[i].y : av[i].x;
                    ffma2(acc[i][j], a, wv[j]);
                }
        }
    }
    // hadd + lane-major stores: value idx = i*CT + j
#pragma unroll
    for (int i = 0; i < 4; i++) {
        if constexpr (CT == 4) {
            float4 v = make_float4(hadd2(acc[i][0]), hadd2(acc[i][1]),
                                   hadd2(acc[i][2]), hadd2(acc[i][3]));
            *reinterpret_cast<float4*>(pb + i * 4) = v;
        } else {
            float2 v = make_float2(hadd2(acc[i][0]), hadd2(acc[i][1]));
            *reinterpret_cast<float2*>(pb + i * 2) = v;
        }
    }
}

// ---- reduce 4 K-quarter slots -> dst[16 x N] (+bias, opt ReLU) -------------
// N=128: thread t -> row r=t>>5, ch2=(t>>4)&1, cg=t&15; cols 64ch2+cg+16j.
template<bool RELU>
__device__ __forceinline__ void reduce128(const float* __restrict__ pbuf,
                                          const float* __restrict__ bias,
                                          float* __restrict__ dst,
                                          int SOUT, int tid) {
    const int r = tid >> 5, ch2 = (tid >> 4) & 1, cg = tid & 15;
    const int hp = r >> 3, rg = (r >> 2) & 1, ip = r & 3;
    const int off = (2 * hp + ch2) * SUB + (rg * 16 + cg) * PL + ip * 4;

    float s[4];
#pragma unroll
    for (int j = 0; j < 4; j++) s[j] = bias[64 * ch2 + cg + 16 * j];
#pragma unroll
    for (int b = 0; b < 4; b++) {
        float4 t4 = *reinterpret_cast<const float4*>(pbuf + b * PSLOT + off);
        s[0] += t4.x; s[1] += t4.y; s[2] += t4.z; s[3] += t4.w;
    }
    float* o = dst + r * SOUT + 64 * ch2 + cg;
#pragma unroll
    for (int j = 0; j < 4; j++) {
        float v = s[j];
        if (RELU) v = fmaxf(v, 0.0f);
        o[16 * j] = v;
    }
}

// N=64: thread t -> row r=t>>5, ch2=(t>>4)&1, cg=t&15; cols 32ch2+cg+16j, j<2.
__device__ __forceinline__ void reduce64(const float* __restrict__ pbuf,
                                         const float* __restrict__ bias,
                                         float* __restrict__ dst,
                                         int SOUT, int tid) {
    const int r = tid >> 5, ch2 = (tid >> 4) & 1, cg = tid & 15;
    const int hp = r >> 3, rg = (r >> 2) & 1, ip = r & 3;
    const int off = (2 * hp + ch2) * SUB + (rg * 16 + cg) * PL + ip * 2;

    float s0 = bias[32 * ch2 + cg];
    float s1 = bias[32 * ch2 + cg + 16];
#pragma unroll
    for (int b = 0; b < 4; b++) {
        float2 t2 = *reinterpret_cast<const float2*>(pbuf + b * PSLOT + off);
        s0 += t2.x; s1 += t2.y;
    }
    float* o = dst + r * SOUT + 32 * ch2 + cg;
    o[0]  = s0;
    o[16] = s1;
}

// ---------------------------------------------------------------------------
__global__ void __launch_bounds__(NTHREADS, 1)
node_kernel(const float* __restrict__ y0, const float* __restrict__ ts,
            const float* __restrict__ w0, const float* __restrict__ b0,
            const float* __restrict__ w1, const float* __restrict__ b1,
            const float* __restrict__ w2, const float* __restrict__ b2,
            float* __restrict__ out, int T) {
    extern __shared__ ulonglong2 smem_w[];
    ulonglong2* wq0 = smem_w;
    ulonglong2* wq1 = wq0 + WE0;
    ulonglong2* wq2 = wq1 + WE1;
    float* fb   = reinterpret_cast<float*>(wq2 + WE2);
    float* sb0  = fb;  fb += 128;
    float* sb1  = fb;  fb += 128;
    float* sb2  = fb;  fb += 64;
    float* act0 = fb;  fb += M_TILE * SA0;
    float* act1 = fb;  fb += M_TILE * SA1;   // also serves as act2 (aliased)
    float* kbuf = fb;  fb += 6 * KBSTG;
    float* ysh  = fb;  fb += M_TILE * 64;
    float* pbuf = fb;

    const int tid  = threadIdx.x;
    const int lane = tid & 31;
    const int warp = tid >> 5;
    const int q    = warp >> 2;              // K quarter 0..3
    const int h    = (warp >> 1) & 1;        // row half
    const int ch   = warp & 1;               // col half
    const int rowg = lane >> 4;
    const int colg = lane & 15;
    const int rowbase = 8 * h + 4 * rowg;
    const int row0 = blockIdx.x * M_TILE;

    // ---- setup: packed col-pair weights (v10/v11 layout) --------------------
    for (int e = tid; e < WE0; e += NTHREADS) {
        int kp = e >> 6, m = (e >> 4) & 3, cg = e & 15;
        int c = cg + 32 * m;
        int k0 = 2 * kp, k1 = 2 * kp + 1;
        float a0 = (k0 < 65) ? w0[c * 65 + k0] : 0.0f;
        float a1 = (k1 < 65) ? w0[c * 65 + k1] : 0.0f;
        float c0v = (k0 < 65) ? w0[(c + 16) * 65 + k0] : 0.0f;
        float c1v = (k1 < 65) ? w0[(c + 16) * 65 + k1] : 0.0f;
        ulonglong2 v; v.x = pack2(a0, a1); v.y = pack2(c0v, c1v);
        wq0[e] = v;
    }
    for (int e = tid; e < WE1; e += NTHREADS) {
        int kp = e >> 6, m = (e >> 4) & 3, cg = e & 15;
        int c = cg + 32 * m;
        ulonglong2 v;
        v.x = pack2(w1[c * 128 + 2 * kp], w1[c * 128 + 2 * kp + 1]);
        v.y = pack2(w1[(c + 16) * 128 + 2 * kp], w1[(c + 16) * 128 + 2 * kp + 1]);
        wq1[e] = v;
    }
    for (int e = tid; e < WE2; e += NTHREADS) {
        int kp = e >> 5, m = (e >> 4) & 1, cg = e & 15;
        int c = cg + 32 * m;
        ulonglong2 v;
        v.x = pack2(w2[c * 128 + 2 * kp], w2[c * 128 + 2 * kp + 1]);
        v.y = pack2(w2[(c + 16) * 128 + 2 * kp], w2[(c + 16) * 128 + 2 * kp + 1]);
        wq2[e] = v;
    }
    for (int i = tid; i < 128; i += NTHREADS) { sb0[i] = b0[i]; sb1[i] = b1[i]; }
    for (int i = tid; i < 64;  i += NTHREADS) sb2[i] = b2[i];
    for (int i = tid; i < M_TILE * 64; i += NTHREADS)
        ysh[i] = y0[row0 * 64 + i];
    if (tid < M_TILE) {                       // zero act0 pad cols 65..79
#pragma unroll
        for (int c = 65; c < 80; c++) act0[tid * SA0 + c] = 0.0f;
    }
    __syncthreads();

    const float dt = ts[1] - ts[0];
    const int steps = T - 1;

    // lane-fixed stream pointers
    float* pbW = pbuf + q * PSLOT + (2 * h + ch) * SUB + lane * PL;
    const ulonglong2* w0W = wq0 + (q * KPW0) * 64 + ch * 32 + colg;
    const ulonglong2* w1W = wq1 + (q * KPW1) * 64 + ch * 32 + colg;
    const ulonglong2* w2W = wq2 + (q * KPW2) * 32 + ch * 16 + colg;
    const float* a0W = act0 + rowbase * SA0 + 2 * (q * KPW0);
    const float* a1W = act1 + rowbase * SA1 + 2 * (q * KPW1);
    const float* a2W = act1 + rowbase * SA1 + 2 * (q * KPW2);   // act2 == act1

    // warp-local prologue: rows 8h+(lane>>2), cols [20q+10ch, +10)
    const int prow = 8 * h + (lane >> 2);
    const int cbase = 20 * q + 10 * ch;
    const int csub  = lane & 3;
    const float* kbRow = kbuf + prow * SKB;
    float* yRow = ysh + prow * 64;
    const int pairbar = 1 + (q * 2 + h);      // named barrier id 1..8

    for (int st = 0; st < steps; st++) {
        const float t = ts[st];
        for (int s = 0; s < 6; s++) {
            // ---- warp-local prologue (+ fused Tsit5 y-update at s==0) ------
            const float ts_ = fmaf(d_cs[s], dt, t);
#pragma unroll
            for (int cc = 0; cc < 3; cc++) {
                const int pc = csub + 4 * cc;
                if (pc >= 10) break;
                const int ac = cbase + pc;
                if (ac == 0) { act0[prow * SA0] = ts_; continue; }
                const int yc = ac - 1;
                if (yc >= 64) continue;
                float yv = yRow[yc];
                if (s == 0) {
                    if (st > 0) {
                        float acc = d_B[0] * kbRow[yc];
#pragma unroll
                        for (int j = 1; j < 6; j++)
                            acc = fmaf(d_B[j], kbRow[j * KBSTG + yc], acc);
                        yv = fmaf(dt, acc, yv);
                        yRow[yc] = yv;
                    }
                    act0[prow * SA0 + ac] = yv;
                } else {
                    float acc = d_A[s][0] * kbRow[yc];
                    for (int j = 1; j < s; j++)
                        acc = fmaf(d_A[s][j], kbRow[j * KBSTG + yc], acc);
                    act0[prow * SA0 + ac] = fmaf(dt, acc, yv);
                }
            }
            // pair barrier: the two (q,h,*) warps exchange their act0 halves
            asm volatile("bar.sync %0, %1;" :: "r"(pairbar), "r"(64) : "memory");

            stream_tile<4, KPW0, SA0, 64>(a0W, w0W, pbW);
            __syncthreads();
            reduce128<true>(pbuf, sb0, act1, SA1, tid);
            __syncthreads();

            stream_tile<4, KPW1, SA1, 64>(a1W, w1W, pbW);
            __syncthreads();
            reduce128<true>(pbuf, sb1, act1, SA1, tid);
            __syncthreads();

            stream_tile<2, KPW2, SA1, 32>(a2W, w2W, pbW);
            __syncthreads();
            reduce64(pbuf, sb2, kbuf + s * KBSTG, SKB, tid);
            __syncthreads();
        }
    }

    // ---- final fused y-update -> out ----------------------------------------
#pragma unroll
    for (int cc = 0; cc < 3; cc++) {
        const int pc = csub + 4 * cc;
        if (pc >= 10) break;
        const int ac = cbase + pc;
        if (ac == 0) continue;
        const int yc = ac - 1;
        if (yc >= 64) continue;
        float acc = d_B[0] * kbRow[yc];
#pragma unroll
        for (int j = 1; j < 6; j++)
            acc = fmaf(d_B[j], kbRow[j * KBSTG + yc], acc);
        out[(row0 + prow) * 64 + yc] = fmaf(dt, acc, yRow[yc]);
    }
}

// ---------------------------------------------------------------------------
extern "C" void kernel_launch(void* const* d_in, const int* in_sizes, int n_in,
                              void* d_out, int out_size) {
    const float* y0 = (const float*)d_in[0];
    const float* ts = (const float*)d_in[1];
    const float* w0 = (const float*)d_in[2];
    const float* b0 = (const float*)d_in[3];
    const float* w1 = (const float*)d_in[4];
    const float* b1 = (const float*)d_in[5];
    const float* w2 = (const float*)d_in[6];
    const float* b2 = (const float*)d_in[7];

    const int B = in_sizes[0] / 64;   // batch rows
    const int T = in_sizes[1];        // number of time points

    cudaFuncSetAttribute(node_kernel,
                         cudaFuncAttributeMaxDynamicSharedMemorySize, SMEM_BYTES);

    node_kernel<<<B / M_TILE, NTHREADS, SMEM_BYTES>>>(
        y0, ts, w0, b0, w1, b1, w2, b2, (float*)d_out, T);
}

// round 13
// speedup vs baseline: 1.2859x; 1.0362x over previous
#include <cuda_runtime.h>

// ---------------------------------------------------------------------------
// NeuralODE Tsit5 — persistent fused kernel, v13 "phase-shifted groups".
// = v12 (16 warps, lane tile 4x4, packed weights, lane-major partials) but
// the CTA is split into TWO independent 8-warp groups (group g owns batch
// rows [8g, 8g+8)) synchronized by per-group named barriers (bar.sync g+1,
// 256). Groups share only read-only weights, drift out of phase, and fill
// each other's barrier/latency bubbles on every SMSP.
// ---------------------------------------------------------------------------

#define NTHREADS 512
#define M_TILE   16

__constant__ float d_cs[6] = {0.0f, 0.161f, 0.327f, 0.9f, 0.9800255409045097f, 1.0f};
__constant__ float d_A[6][5] = {
    {0.f, 0.f, 0.f, 0.f, 0.f},
    {0.161f, 0.f, 0.f, 0.f, 0.f},
    {-0.008480655492356989f, 0.335480655492357f, 0.f, 0.f, 0.f},
    {2.8971530571054935f, -6.359448489975075f, 4.3622954328695815f, 0.f, 0.f},
    {5.325864828439257f, -11.748883564062828f, 7.4955393428898365f, -0.09249506636175525f, 0.f},
    {5.86145544294642f, -12.92096931784711f, 8.159367898576159f, -0.071584973281401f, -0.028269050394068383f}
};
__constant__ float d_B[6] = {
    0.09646076681806523f, 0.01f, 0.4798896504144996f,
    1.379008574103742f, -3.290069515436081f, 2.324710524099774f
};

typedef unsigned long long u64;

__device__ __forceinline__ u64 pack2(float x, float y) {
    u64 r; asm("mov.b64 %0, {%1, %2};" : "=l"(r) : "f"(x), "f"(y)); return r;
}
__device__ __forceinline__ float hadd2(u64 v) {
    float2 f; asm("mov.b64 {%0, %1}, %2;" : "=f"(f.x), "=f"(f.y) : "l"(v));
    return f.x + f.y;
}
__device__ __forceinline__ void ffma2(u64& d, u64 a, u64 b) {
    asm("fma.rn.f32x2 %0, %1, %2, %0;" : "+l"(d) : "l"(a), "l"(b));
}

// ---- sizes (floats unless noted) -------------------------------------------
#define KP0 40          // layer0 k-pairs (80 = t + 64 y + 15 pad)
#define KPW0 10
#define KP1 64
#define KPW1 16
#define KP2 64
#define KPW2 16
#define SA0 84
#define SA1 132
#define SKB 68
#define KBSTG (M_TILE*SKB)
#define PL 20                 // lane partial stride (16 vals + 4 pad; 80B CF)
#define SUB (32*PL)           // per (g,ch) sub-block in a slot
#define PSLOT (4*SUB)         // per K-quarter slot

// weight entries (ulonglong2): per kp, N=128 -> 64 entries, N=64 -> 32
#define WE0 (KP0*64)
#define WE1 (KP1*64)
#define WE2 (KP2*32)
#define F32_WORDS (128+128+64 + M_TILE*SA0 + M_TILE*SA1 + 6*KBSTG + M_TILE*64 + 4*PSLOT)
#define SMEM_BYTES ((WE0+WE1+WE2)*16 + F32_WORDS*4)   // ~220 KB

// ---- stream: warp (q,g,ch), lane tile 4 rows x CT cols ----------------------
template<int CT, int KPW, int SIN, int NENT>
__device__ __forceinline__ void stream_tile(const float* __restrict__ aBase,
                                            const ulonglong2* __restrict__ wBase,
                                            float* __restrict__ pb) {
    u64 acc[4][CT];
#pragma unroll
    for (int i = 0; i < 4; i++)
#pragma unroll
        for (int j = 0; j < CT; j++) acc[i][j] = 0ull;

#pragma unroll 2
    for (int kp2 = 0; kp2 < KPW / 2; kp2++) {
        ulonglong2 av[4];
#pragma unroll
        for (int i = 0; i < 4; i++)
            av[i] = *reinterpret_cast<const ulonglong2*>(aBase + i * SIN + 4 * kp2);
#pragma unroll
        for (int kk = 0; kk < 2; kk++) {
            const int kp = 2 * kp2 + kk;
            u64 wv[CT];
            if constexpr (CT == 4) {
                ulonglong2 wA = wBase[kp * NENT];
                ulonglong2 wB = wBase[kp * NENT + 16];
                wv[0] = wA.x; wv[1] = wA.y; wv[2] = wB.x; wv[3] = wB.y;
            } else {
                ulonglong2 wA = wBase[kp * NENT];
                wv[0] = wA.x; wv[1] = wA.y;
            }
#pragma unroll
            for (int j = 0; j < CT; j++)
#pragma unroll
                for (int i = 0; i < 4; i++) {
                    u64 a = kk ? av[i].y : av[i].x;
                    ffma2(acc[i][j], a, wv[j]);
                }
        }
    }
#pragma unroll
    for (int i = 0; i < 4; i++) {
        if constexpr (CT == 4) {
            float4 v = make_float4(hadd2(acc[i][0]), hadd2(acc[i][1]),
                                   hadd2(acc[i][2]), hadd2(acc[i][3]));
            *reinterpret_cast<float4*>(pb + i * 4) = v;
        } else {
            float2 v = make_float2(hadd2(acc[i][0]), hadd2(acc[i][1]));
            *reinterpret_cast<float2*>(pb + i * 2) = v;
        }
    }
}

// ---- group-local reduce: 4 K-quarter slots -> dst rows [8g,8g+8) -----------
// tp = gwarp*32 + lane (0..255). N=128: r_loc=tp>>5, ch2=(tp>>4)&1, cg=tp&15.
template<bool RELU>
__device__ __forceinline__ void reduce128(const float* __restrict__ pbuf,
                                          const float* __restrict__ bias,
                                          float* __restrict__ dst,
                                          int SOUT, int g, int tp) {
    const int rl = tp >> 5, ch2 = (tp >> 4) & 1, cg = tp & 15;
    const int rg = rl >> 2, ip = rl & 3;
    const int off = (2 * g + ch2) * SUB + (rg * 16 + cg) * PL + ip * 4;

    float s[4];
#pragma unroll
    for (int j = 0; j < 4; j++) s[j] = bias[64 * ch2 + cg + 16 * j];
#pragma unroll
    for (int b = 0; b < 4; b++) {
        float4 t4 = *reinterpret_cast<const float4*>(pbuf + b * PSLOT + off);
        s[0] += t4.x; s[1] += t4.y; s[2] += t4.z; s[3] += t4.w;
    }
    float* o = dst + (8 * g + rl) * SOUT + 64 * ch2 + cg;
#pragma unroll
    for (int j = 0; j < 4; j++) {
        float v = s[j];
        if (RELU) v = fmaxf(v, 0.0f);
        o[16 * j] = v;
    }
}

__device__ __forceinline__ void reduce64(const float* __restrict__ pbuf,
                                         const float* __restrict__ bias,
                                         float* __restrict__ dst,
                                         int SOUT, int g, int tp) {
    const int rl = tp >> 5, ch2 = (tp >> 4) & 1, cg = tp & 15;
    const int rg = rl >> 2, ip = rl & 3;
    const int off = (2 * g + ch2) * SUB + (rg * 16 + cg) * PL + ip * 2;

    float s0 = bias[32 * ch2 + cg];
    float s1 = bias[32 * ch2 + cg + 16];
#pragma unroll
    for (int b = 0; b < 4; b++) {
        float2 t2 = *reinterpret_cast<const float2*>(pbuf + b * PSLOT + off);
        s0 += t2.x; s1 += t2.y;
    }
    float* o = dst + (8 * g + rl) * SOUT + 32 * ch2 + cg;
    o[0]  = s0;
    o[16] = s1;
}

// ---------------------------------------------------------------------------
__global__ void __launch_bounds__(NTHREADS, 1)
node_kernel(const float* __restrict__ y0, const float* __restrict__ ts,
            const float* __restrict__ w0, const float* __restrict__ b0,
            const float* __restrict__ w1, const float* __restrict__ b1,
            const float* __restrict__ w2, const float* __restrict__ b2,
            float* __restrict__ out, int T) {
    extern __shared__ ulonglong2 smem_w[];
    ulonglong2* wq0 = smem_w;
    ulonglong2* wq1 = wq0 + WE0;
    ulonglong2* wq2 = wq1 + WE1;
    float* fb   = reinterpret_cast<float*>(wq2 + WE2);
    float* sb0  = fb;  fb += 128;
    float* sb1  = fb;  fb += 128;
    float* sb2  = fb;  fb += 64;
    float* act0 = fb;  fb += M_TILE * SA0;
    float* act1 = fb;  fb += M_TILE * SA1;   // also serves as act2 (aliased)
    float* kbuf = fb;  fb += 6 * KBSTG;
    float* ysh  = fb;  fb += M_TILE * 64;
    float* pbuf = fb;

    const int tid  = threadIdx.x;
    const int lane = tid & 31;
    const int warp = tid >> 5;
    const int g    = warp >> 3;              // group 0..1 (rows [8g,8g+8))
    const int gw   = warp & 7;               // warp within group
    const int q    = gw >> 1;                // K quarter 0..3
    const int ch   = gw & 1;                 // col half
    const int rowg = lane >> 4;
    const int colg = lane & 15;
    const int rowbase = 8 * g + 4 * rowg;
    const int tp   = gw * 32 + lane;         // thread index within group
    const int row0 = blockIdx.x * M_TILE;

    // ---- setup: packed col-pair weights -------------------------------------
    for (int e = tid; e < WE0; e += NTHREADS) {
        int kp = e >> 6, m = (e >> 4) & 3, cg = e & 15;
        int c = cg + 32 * m;
        int k0 = 2 * kp, k1 = 2 * kp + 1;
        float a0 = (k0 < 65) ? w0[c * 65 + k0] : 0.0f;
        float a1 = (k1 < 65) ? w0[c * 65 + k1] : 0.0f;
        float c0v = (k0 < 65) ? w0[(c + 16) * 65 + k0] : 0.0f;
        float c1v = (k1 < 65) ? w0[(c + 16) * 65 + k1] : 0.0f;
        ulonglong2 v; v.x = pack2(a0, a1); v.y = pack2(c0v, c1v);
        wq0[e] = v;
    }
    for (int e = tid; e < WE1; e += NTHREADS) {
        int kp = e >> 6, m = (e >> 4) & 3, cg = e & 15;
        int c = cg + 32 * m;
        ulonglong2 v;
        v.x = pack2(w1[c * 128 + 2 * kp], w1[c * 128 + 2 * kp + 1]);
        v.y = pack2(w1[(c + 16) * 128 + 2 * kp], w1[(c + 16) * 128 + 2 * kp + 1]);
        wq1[e] = v;
    }
    for (int e = tid; e < WE2; e += NTHREADS) {
        int kp = e >> 5, m = (e >> 4) & 1, cg = e & 15;
        int c = cg + 32 * m;
        ulonglong2 v;
        v.x = pack2(w2[c * 128 + 2 * kp], w2[c * 128 + 2 * kp + 1]);
        v.y = pack2(w2[(c + 16) * 128 + 2 * kp], w2[(c + 16) * 128 + 2 * kp + 1]);
        wq2[e] = v;
    }
    for (int i = tid; i < 128; i += NTHREADS) { sb0[i] = b0[i]; sb1[i] = b1[i]; }
    for (int i = tid; i < 64;  i += NTHREADS) sb2[i] = b2[i];
    for (int i = tid; i < M_TILE * 64; i += NTHREADS)
        ysh[i] = y0[row0 * 64 + i];
    if (tid < M_TILE) {                       // zero act0 pad cols 65..79
#pragma unroll
        for (int c = 65; c < 80; c++) act0[tid * SA0 + c] = 0.0f;
    }
    __syncthreads();    // only CTA-wide barrier; groups independent after this

    const float dt = ts[1] - ts[0];
    const int steps = T - 1;

    // lane-fixed stream pointers
    float* pbW = pbuf + q * PSLOT + (2 * g + ch) * SUB + lane * PL;
    const ulonglong2* w0W = wq0 + (q * KPW0) * 64 + ch * 32 + colg;
    const ulonglong2* w1W = wq1 + (q * KPW1) * 64 + ch * 32 + colg;
    const ulonglong2* w2W = wq2 + (q * KPW2) * 32 + ch * 16 + colg;
    const float* a0W = act0 + rowbase * SA0 + 2 * (q * KPW0);
    const float* a1W = act1 + rowbase * SA1 + 2 * (q * KPW1);
    const float* a2W = act1 + rowbase * SA1 + 2 * (q * KPW2);   // act2 == act1

    // warp-local prologue: rows 8g+(lane>>2), cols [20q+10ch, +10)
    const int prow = 8 * g + (lane >> 2);
    const int cbase = 20 * q + 10 * ch;
    const int csub  = lane & 3;
    const float* kbRow = kbuf + prow * SKB;
    float* yRow = ysh + prow * 64;
    const int gbar = 1 + g;                   // named barrier id per group

#define BARG() asm volatile("bar.sync %0, %1;" :: "r"(gbar), "r"(256) : "memory")

    for (int st = 0; st < steps; st++) {
        const float t = ts[st];
        for (int s = 0; s < 6; s++) {
            // ---- warp-local prologue (+ fused Tsit5 y-update at s==0) ------
            const float ts_ = fmaf(d_cs[s], dt, t);
#pragma unroll
            for (int cc = 0; cc < 3; cc++) {
                const int pc = csub + 4 * cc;
                if (pc >= 10) break;
                const int ac = cbase + pc;
                if (ac == 0) { act0[prow * SA0] = ts_; continue; }
                const int yc = ac - 1;
                if (yc >= 64) continue;
                float yv = yRow[yc];
                if (s == 0) {
                    if (st > 0) {
                        float acc = d_B[0] * kbRow[yc];
#pragma unroll
                        for (int j = 1; j < 6; j++)
                            acc = fmaf(d_B[j], kbRow[j * KBSTG + yc], acc);
                        yv = fmaf(dt, acc, yv);
                        yRow[yc] = yv;
                    }
                    act0[prow * SA0 + ac] = yv;
                } else {
                    float acc = d_A[s][0] * kbRow[yc];
                    for (int j = 1; j < s; j++)
                        acc = fmaf(d_A[s][j], kbRow[j * KBSTG + yc], acc);
                    act0[prow * SA0 + ac] = fmaf(dt, acc, yv);
                }
            }
            BARG();

            stream_tile<4, KPW0, SA0, 64>(a0W, w0W, pbW);
            BARG();
            reduce128<true>(pbuf, sb0, act1, SA1, g, tp);
            BARG();

            stream_tile<4, KPW1, SA1, 64>(a1W, w1W, pbW);
            BARG();
            reduce128<true>(pbuf, sb1, act1, SA1, g, tp);
            BARG();

            stream_tile<2, KPW2, SA1, 32>(a2W, w2W, pbW);
            BARG();
            reduce64(pbuf, sb2, kbuf + s * KBSTG, SKB, g, tp);
            BARG();
        }
    }

    // ---- final fused y-update -> out ----------------------------------------
#pragma unroll
    for (int cc = 0; cc < 3; cc++) {
        const int pc = csub + 4 * cc;
        if (pc >= 10) break;
        const int ac = cbase + pc;
        if (ac == 0) continue;
        const int yc = ac - 1;
        if (yc >= 64) continue;
        float acc = d_B[0] * kbRow[yc];
#pragma unroll
        for (int j = 1; j < 6; j++)
            acc = fmaf(d_B[j], kbRow[j * KBSTG + yc], acc);
        out[(row0 + prow) * 64 + yc] = fmaf(dt, acc, yRow[yc]);
    }
#undef BARG
}

// ---------------------------------------------------------------------------
extern "C" void kernel_launch(void* const* d_in, const int* in_sizes, int n_in,
                              void* d_out, int out_size) {
    const float* y0 = (const float*)d_in[0];
    const float* ts = (const float*)d_in[1];
    const float* w0 = (const float*)d_in[2];
    const float* b0 = (const float*)d_in[3];
    const float* w1 = (const float*)d_in[4];
    const float* b1 = (const float*)d_in[5];
    const float* w2 = (const float*)d_in[6];
    const float* b2 = (const float*)d_in[7];

    const int B = in_sizes[0] / 64;   // batch rows
    const int T = in_sizes[1];        // number of time points

    cudaFuncSetAttribute(node_kernel,
                         cudaFuncAttributeMaxDynamicSharedMemorySize, SMEM_BYTES);

    node_kernel<<<B / M_TILE, NTHREADS, SMEM_BYTES>>>(
        y0, ts, w0, b0, w1, b1, w2, b2, (float*)d_out, T);
}

// round 14
// speedup vs baseline: 1.3651x; 1.0616x over previous
#include <cuda_runtime.h>

// ---------------------------------------------------------------------------
// NeuralODE Tsit5 — persistent fused kernel, v14 "fused RK epilogue".
// = v13 (two phase-shifted 8-warp groups, packed weights, lane-major
// partials) but the separate RK prologue phase is FUSED into the reduce64:
// the thread that reduces k_s[row][c] immediately computes the next stage's
// act0[row][c] (and at s==5 the Tsit5 y-update + final output) using its
// register-resident k_s. 6 group barriers per stage instead of 7, and all
// epilogue SMEM accesses are warp-contiguous.
// ---------------------------------------------------------------------------

#define NTHREADS 512
#define M_TILE   16

__constant__ float d_cs[6] = {0.0f, 0.161f, 0.327f, 0.9f, 0.9800255409045097f, 1.0f};
__constant__ float d_A[6][5] = {
    {0.f, 0.f, 0.f, 0.f, 0.f},
    {0.161f, 0.f, 0.f, 0.f, 0.f},
    {-0.008480655492356989f, 0.335480655492357f, 0.f, 0.f, 0.f},
    {2.8971530571054935f, -6.359448489975075f, 4.3622954328695815f, 0.f, 0.f},
    {5.325864828439257f, -11.748883564062828f, 7.4955393428898365f, -0.09249506636175525f, 0.f},
    {5.86145544294642f, -12.92096931784711f, 8.159367898576159f, -0.071584973281401f, -0.028269050394068383f}
};
__constant__ float d_B[6] = {
    0.09646076681806523f, 0.01f, 0.4798896504144996f,
    1.379008574103742f, -3.290069515436081f, 2.324710524099774f
};

typedef unsigned long long u64;

__device__ __forceinline__ u64 pack2(float x, float y) {
    u64 r; asm("mov.b64 %0, {%1, %2};" : "=l"(r) : "f"(x), "f"(y)); return r;
}
__device__ __forceinline__ float hadd2(u64 v) {
    float2 f; asm("mov.b64 {%0, %1}, %2;" : "=f"(f.x), "=f"(f.y) : "l"(v));
    return f.x + f.y;
}
__device__ __forceinline__ void ffma2(u64& d, u64 a, u64 b) {
    asm("fma.rn.f32x2 %0, %1, %2, %0;" : "+l"(d) : "l"(a), "l"(b));
}

// ---- sizes (floats unless noted) -------------------------------------------
#define KP0 40          // layer0 k-pairs (80 = t + 64 y + 15 pad)
#define KPW0 10
#define KP1 64
#define KPW1 16
#define KP2 64
#define KPW2 16
#define SA0 84
#define SA1 132
#define SKB 68
#define KBSTG (M_TILE*SKB)
#define PL 20                 // lane partial stride (16 vals + 4 pad)
#define SUB (32*PL)           // per (g,ch) sub-block in a slot
#define PSLOT (4*SUB)         // per K-quarter slot

#define WE0 (KP0*64)
#define WE1 (KP1*64)
#define WE2 (KP2*32)
#define F32_WORDS (128+128+64 + M_TILE*SA0 + M_TILE*SA1 + 6*KBSTG + M_TILE*64 + 4*PSLOT)
#define SMEM_BYTES ((WE0+WE1+WE2)*16 + F32_WORDS*4)   // ~220 KB

// ---- stream: warp (q,g,ch), lane tile 4 rows x CT cols ----------------------
template<int CT, int KPW, int SIN, int NENT>
__device__ __forceinline__ void stream_tile(const float* __restrict__ aBase,
                                            const ulonglong2* __restrict__ wBase,
                                            float* __restrict__ pb) {
    u64 acc[4][CT];
#pragma unroll
    for (int i = 0; i < 4; i++)
#pragma unroll
        for (int j = 0; j < CT; j++) acc[i][j] = 0ull;

#pragma unroll 2
    for (int kp2 = 0; kp2 < KPW / 2; kp2++) {
        ulonglong2 av[4];
#pragma unroll
        for (int i = 0; i < 4; i++)
            av[i] = *reinterpret_cast<const ulonglong2*>(aBase + i * SIN + 4 * kp2);
#pragma unroll
        for (int kk = 0; kk < 2; kk++) {
            const int kp = 2 * kp2 + kk;
            u64 wv[CT];
            if constexpr (CT == 4) {
                ulonglong2 wA = wBase[kp * NENT];
                ulonglong2 wB = wBase[kp * NENT + 16];
                wv[0] = wA.x; wv[1] = wA.y; wv[2] = wB.x; wv[3] = wB.y;
            } else {
                ulonglong2 wA = wBase[kp * NENT];
                wv[0] = wA.x; wv[1] = wA.y;
            }
#pragma unroll
            for (int j = 0; j < CT; j++)
#pragma unroll
                for (int i = 0; i < 4; i++) {
                    u64 a = kk ? av[i].y : av[i].x;
                    ffma2(acc[i][j], a, wv[j]);
                }
        }
    }
#pragma unroll
    for (int i = 0; i < 4; i++) {
        if constexpr (CT == 4) {
            float4 v = make_float4(hadd2(acc[i][0]), hadd2(acc[i][1]),
                                   hadd2(acc[i][2]), hadd2(acc[i][3]));
            *reinterpret_cast<float4*>(pb + i * 4) = v;
        } else {
            float2 v = make_float2(hadd2(acc[i][0]), hadd2(acc[i][1]));
            *reinterpret_cast<float2*>(pb + i * 2) = v;
        }
    }
}

// ---- group-local reduce (N=128 layers): 4 slots -> dst rows [8g,8g+8) ------
template<bool RELU>
__device__ __forceinline__ void reduce128(const float* __restrict__ pbuf,
                                          const float* __restrict__ bias,
                                          float* __restrict__ dst,
                                          int SOUT, int g, int tp) {
    const int rl = tp >> 5, ch2 = (tp >> 4) & 1, cg = tp & 15;
    const int rg = rl >> 2, ip = rl & 3;
    const int off = (2 * g + ch2) * SUB + (rg * 16 + cg) * PL + ip * 4;

    float s[4];
#pragma unroll
    for (int j = 0; j < 4; j++) s[j] = bias[64 * ch2 + cg + 16 * j];
#pragma unroll
    for (int b = 0; b < 4; b++) {
        float4 t4 = *reinterpret_cast<const float4*>(pbuf + b * PSLOT + off);
        s[0] += t4.x; s[1] += t4.y; s[2] += t4.z; s[3] += t4.w;
    }
    float* o = dst + (8 * g + rl) * SOUT + 64 * ch2 + cg;
#pragma unroll
    for (int j = 0; j < 4; j++) {
        float v = s[j];
        if (RELU) v = fmaxf(v, 0.0f);
        o[16 * j] = v;
    }
}

// ---------------------------------------------------------------------------
__global__ void __launch_bounds__(NTHREADS, 1)
node_kernel(const float* __restrict__ y0, const float* __restrict__ ts,
            const float* __restrict__ w0, const float* __restrict__ b0,
            const float* __restrict__ w1, const float* __restrict__ b1,
            const float* __restrict__ w2, const float* __restrict__ b2,
            float* __restrict__ out, int T) {
    extern __shared__ ulonglong2 smem_w[];
    ulonglong2* wq0 = smem_w;
    ulonglong2* wq1 = wq0 + WE0;
    ulonglong2* wq2 = wq1 + WE1;
    float* fb   = reinterpret_cast<float*>(wq2 + WE2);
    float* sb0  = fb;  fb += 128;
    float* sb1  = fb;  fb += 128;
    float* sb2  = fb;  fb += 64;
    float* act0 = fb;  fb += M_TILE * SA0;
    float* act1 = fb;  fb += M_TILE * SA1;   // also serves as act2 (aliased)
    float* kbuf = fb;  fb += 6 * KBSTG;
    float* ysh  = fb;  fb += M_TILE * 64;
    float* pbuf = fb;

    const int tid  = threadIdx.x;
    const int lane = tid & 31;
    const int warp = tid >> 5;
    const int g    = warp >> 3;              // group 0..1 (rows [8g,8g+8))
    const int gw   = warp & 7;               // warp within group
    const int q    = gw >> 1;                // K quarter 0..3
    const int ch   = gw & 1;                 // col half
    const int rowg = lane >> 4;
    const int colg = lane & 15;
    const int rowbase = 8 * g + 4 * rowg;
    const int tp   = gw * 32 + lane;         // thread index within group
    const int row0 = blockIdx.x * M_TILE;

    // ---- setup: packed col-pair weights -------------------------------------
    for (int e = tid; e < WE0; e += NTHREADS) {
        int kp = e >> 6, m = (e >> 4) & 3, cg = e & 15;
        int c = cg + 32 * m;
        int k0 = 2 * kp, k1 = 2 * kp + 1;
        float a0 = (k0 < 65) ? w0[c * 65 + k0] : 0.0f;
        float a1 = (k1 < 65) ? w0[c * 65 + k1] : 0.0f;
        float c0v = (k0 < 65) ? w0[(c + 16) * 65 + k0] : 0.0f;
        float c1v = (k1 < 65) ? w0[(c + 16) * 65 + k1] : 0.0f;
        ulonglong2 v; v.x = pack2(a0, a1); v.y = pack2(c0v, c1v);
        wq0[e] = v;
    }
    for (int e = tid; e < WE1; e += NTHREADS) {
        int kp = e >> 6, m = (e >> 4) & 3, cg = e & 15;
        int c = cg + 32 * m;
        ulonglong2 v;
        v.x = pack2(w1[c * 128 + 2 * kp], w1[c * 128 + 2 * kp + 1]);
        v.y = pack2(w1[(c + 16) * 128 + 2 * kp], w1[(c + 16) * 128 + 2 * kp + 1]);
        wq1[e] = v;
    }
    for (int e = tid; e < WE2; e += NTHREADS) {
        int kp = e >> 5, m = (e >> 4) & 1, cg = e & 15;
        int c = cg + 32 * m;
        ulonglong2 v;
        v.x = pack2(w2[c * 128 + 2 * kp], w2[c * 128 + 2 * kp + 1]);
        v.y = pack2(w2[(c + 16) * 128 + 2 * kp], w2[(c + 16) * 128 + 2 * kp + 1]);
        wq2[e] = v;
    }
    for (int i = tid; i < 128; i += NTHREADS) { sb0[i] = b0[i]; sb1[i] = b1[i]; }
    for (int i = tid; i < 64;  i += NTHREADS) sb2[i] = b2[i];
    for (int i = tid; i < M_TILE * 64; i += NTHREADS) {
        float v = y0[row0 * 64 + i];
        ysh[i] = v;
        act0[(i >> 6) * SA0 + 1 + (i & 63)] = v;    // initial act0 = [t0, y0]
    }
    if (tid < M_TILE) {
        act0[tid * SA0] = ts[0];
#pragma unroll
        for (int c = 65; c < 80; c++) act0[tid * SA0 + c] = 0.0f;
    }
    __syncthreads();    // only CTA-wide barrier; groups independent after this

    const float dt = ts[1] - ts[0];
    const int steps = T - 1;

    // lane-fixed stream pointers
    float* pbW = pbuf + q * PSLOT + (2 * g + ch) * SUB + lane * PL;
    const ulonglong2* w0W = wq0 + (q * KPW0) * 64 + ch * 32 + colg;
    const ulonglong2* w1W = wq1 + (q * KPW1) * 64 + ch * 32 + colg;
    const ulonglong2* w2W = wq2 + (q * KPW2) * 32 + ch * 16 + colg;
    const float* a0W = act0 + rowbase * SA0 + 2 * (q * KPW0);
    const float* a1W = act1 + rowbase * SA1 + 2 * (q * KPW1);
    const float* a2W = act1 + rowbase * SA1 + 2 * (q * KPW2);   // act2 == act1

    // fused-epilogue mapping: warp gw owns row 8g+gw; lane owns cols c0, c0+16
    // (c0 = 32*ch2 + cg -> contiguous SMEM access within the warp).
    const int erow = 8 * g + gw;
    const int ech2 = (lane >> 4) & 1, ecg = lane & 15;
    const int c0 = 32 * ech2 + ecg;
    const int erg = gw >> 2, eip = gw & 3;
    const int eoff = (2 * g + ech2) * SUB + (erg * 16 + ecg) * PL + eip * 2;
    float* kRow = kbuf + erow * SKB;         // k_j at + j*KBSTG
    float* yRow = ysh + erow * 64;
    float* aRow = act0 + erow * SA0;
    const float bv2a = sb2[c0], bv2b = sb2[c0 + 16];

    const int gbar = 1 + g;

#define BARG() asm volatile("bar.sync %0, %1;" :: "r"(gbar), "r"(256) : "memory")

    for (int st = 0; st < steps; st++) {
        const float t = ts[st];
        for (int s = 0; s < 6; s++) {
            stream_tile<4, KPW0, SA0, 64>(a0W, w0W, pbW);
            BARG();
            reduce128<true>(pbuf, sb0, act1, SA1, g, tp);
            BARG();

            stream_tile<4, KPW1, SA1, 64>(a1W, w1W, pbW);
            BARG();
            reduce128<true>(pbuf, sb1, act1, SA1, g, tp);
            BARG();

            stream_tile<2, KPW2, SA1, 32>(a2W, w2W, pbW);
            BARG();

            // ---- fused: reduce k_s + store + next-stage prologue ------------
            {
                float s0 = bv2a, s1 = bv2b;
#pragma unroll
                for (int b = 0; b < 4; b++) {
                    float2 t2 = *reinterpret_cast<const float2*>(pbuf + b * PSLOT + eoff);
                    s0 += t2.x; s1 += t2.y;
                }
                // k_s -> kbuf (consumed by later stages' prologues)
                kRow[s * KBSTG + c0]      = s0;
                kRow[s * KBSTG + c0 + 16] = s1;

                const float yv0 = yRow[c0], yv1 = yRow[c0 + 16];
                if (s < 5) {
                    // act0 = y + dt * sum_{j<=s} A[s+1][j] k_j  (k_s in regs)
                    float a0acc = 0.0f, a1acc = 0.0f;
                    for (int j = 0; j < s; j++) {
                        a0acc = fmaf(d_A[s + 1][j], kRow[j * KBSTG + c0], a0acc);
                        a1acc = fmaf(d_A[s + 1][j], kRow[j * KBSTG + c0 + 16], a1acc);
                    }
                    a0acc = fmaf(d_A[s + 1][s], s0, a0acc);
                    a1acc = fmaf(d_A[s + 1][s], s1, a1acc);
                    aRow[1 + c0]      = fmaf(dt, a0acc, yv0);
                    aRow[1 + c0 + 16] = fmaf(dt, a1acc, yv1);
                    if (lane == 0) aRow[0] = fmaf(d_cs[s + 1], dt, t);
                } else {
                    // Tsit5 y-update: y += dt * sum_j B[j] k_j  (k_5 in regs)
                    float a0acc = 0.0f, a1acc = 0.0f;
#pragma unroll
                    for (int j = 0; j < 5; j++) {
                        a0acc = fmaf(d_B[j], kRow[j * KBSTG + c0], a0acc);
                        a1acc = fmaf(d_B[j], kRow[j * KBSTG + c0 + 16], a1acc);
                    }
                    a0acc = fmaf(d_B[5], s0, a0acc);
                    a1acc = fmaf(d_B[5], s1, a1acc);
                    const float yn0 = fmaf(dt, a0acc, yv0);
                    const float yn1 = fmaf(dt, a1acc, yv1);
                    yRow[c0] = yn0; yRow[c0 + 16] = yn1;
                    aRow[1 + c0] = yn0; aRow[1 + c0 + 16] = yn1;
                    if (lane == 0) aRow[0] = ts[st + 1];
                    if (st == steps - 1) {
                        out[(row0 + erow) * 64 + c0]      = yn0;
                        out[(row0 + erow) * 64 + c0 + 16] = yn1;
                    }
                }
            }
            BARG();
        }
    }
#undef BARG
}

// ---------------------------------------------------------------------------
extern "C" void kernel_launch(void* const* d_in, const int* in_sizes, int n_in,
                              void* d_out, int out_size) {
    const float* y0 = (const float*)d_in[0];
    const float* ts = (const float*)d_in[1];
    const float* w0 = (const float*)d_in[2];
    const float* b0 = (const float*)d_in[3];
    const float* w1 = (const float*)d_in[4];
    const float* b1 = (const float*)d_in[5];
    const float* w2 = (const float*)d_in[6];
    const float* b2 = (const float*)d_in[7];

    const int B = in_sizes[0] / 64;   // batch rows
    const int T = in_sizes[1];        // number of time points

    cudaFuncSetAttribute(node_kernel,
                         cudaFuncAttributeMaxDynamicSharedMemorySize, SMEM_BYTES);

    node_kernel<<<B / M_TILE, NTHREADS, SMEM_BYTES>>>(
        y0, ts, w0, b0, w1, b1, w2, b2, (float*)d_out, T);
}

// round 16
// speedup vs baseline: 3.6199x; 2.6517x over previous
#include <cuda_runtime.h>
#include <cuda_bf16.h>
#include <cstdint>

// ---------------------------------------------------------------------------
// NeuralODE Tsit5 — v16: mma.sync bf16x3 emulated-fp32 (portable HMMA path;
// tcgen05 rejected by the harness's compute_103 virtual arch).
// CTA = 16 batch rows, 256 threads (8 warps). D[16,8] tiles via
// mma.m16n8k16.row.col.f32.bf16.bf16.f32, 3 passes: hiA*hiB + hiA*loB + loA*hiB.
// Acts & weights pre-packed in FRAGMENT LAYOUT in SMEM: every operand is one
// conflict-free LDS.128; every epilogue value lands in the next layer's
// A-fragment slot with lane'==lane (closed-form mapping). t folded into the
// layer-0 bias (exact f32). Fused RK epilogue (v14). 3 barriers/stage.
// ---------------------------------------------------------------------------

#define NTHREADS 256
#define M_TILE   16

__constant__ float d_cs[6] = {0.0f, 0.161f, 0.327f, 0.9f, 0.9800255409045097f, 1.0f};
__constant__ float d_A[6][5] = {
    {0.f, 0.f, 0.f, 0.f, 0.f},
    {0.161f, 0.f, 0.f, 0.f, 0.f},
    {-0.008480655492356989f, 0.335480655492357f, 0.f, 0.f, 0.f},
    {2.8971530571054935f, -6.359448489975075f, 4.3622954328695815f, 0.f, 0.f},
    {5.325864828439257f, -11.748883564062828f, 7.4955393428898365f, -0.09249506636175525f, 0.f},
    {5.86145544294642f, -12.92096931784711f, 8.159367898576159f, -0.071584973281401f, -0.028269050394068383f}
};
__constant__ float d_B[6] = {
    0.09646076681806523f, 0.01f, 0.4798896504144996f,
    1.379008574103742f, -3.290069515436081f, 2.324710524099774f
};

// ---- helpers ----------------------------------------------------------------
__device__ __forceinline__ uint32_t pk2(float x, float y) {
    __nv_bfloat162 h = __floats2bfloat162_rn(x, y);   // .x = low half
    return *reinterpret_cast<uint32_t*>(&h);
}
__device__ __forceinline__ float bflo(float v) {
    return v - __bfloat162float(__float2bfloat16(v));
}
__device__ __forceinline__ void mma16816(float& d0, float& d1, float& d2, float& d3,
                                         uint32_t a0, uint32_t a1, uint32_t a2, uint32_t a3,
                                         uint32_t b0, uint32_t b1) {
    asm volatile("mma.sync.aligned.m16n8k16.row.col.f32.bf16.bf16.f32 "
        "{%0,%1,%2,%3}, {%4,%5,%6,%7}, {%8,%9}, {%0,%1,%2,%3};"
        : "+f"(d0), "+f"(d1), "+f"(d2), "+f"(d3)
        : "r"(a0), "r"(a1), "r"(a2), "r"(a3), "r"(b0), "r"(b1));
}

// ---- SMEM byte offsets -------------------------------------------------------
// Weight frags: uint4 {b0h,b1h,b0l,b1l} per (tile,kstep,lane).
#define O_WF0 0              /* [16][4][32] uint4 = 32768 B */
#define O_WF1 32768          /* [16][8][32] uint4 = 65536 B */
#define O_WF2 98304          /* [8][8][32]  uint4 = 32768 B */
// Act frags: u32 a_j at [kstep][lane][j] (uint4 per lane per kstep).
#define O_A0H 131072         /* [4][32][4] u32 = 2048 B */
#define O_A0L 133120
#define O_A1H 135168         /* [8][32][4] u32 = 4096 B */
#define O_A1L 139264
#define O_A2H 143360
#define O_A2L 147456
#define O_KB  151552         /* f32 [6][16][68] = 26112 B (only k0..k4 used) */
#define O_Y   177664         /* f32 [16][64] = 4096 B */
#define SMEM_BYTES 181760
#define SKB 68
#define KBSTG (16*SKB)

// ---- 2-tile GEMM slice: warp computes D for tiles T and T+8 ------------------
template<int KS>
__device__ __forceinline__ void gemm2(const uint4* __restrict__ aH,
                                      const uint4* __restrict__ aL,
                                      const uint4* __restrict__ wfA,
                                      const uint4* __restrict__ wfB,
                                      int lane, float* dA, float* dB) {
#pragma unroll
    for (int kk = 0; kk < KS; kk++) {
        uint4 ah = aH[kk * 32 + lane];
        uint4 al = aL[kk * 32 + lane];
        uint4 wa = wfA[kk * 32 + lane];
        uint4 wb = wfB[kk * 32 + lane];
        mma16816(dA[0], dA[1], dA[2], dA[3], ah.x, ah.y, ah.z, ah.w, wa.x, wa.y);
        mma16816(dA[0], dA[1], dA[2], dA[3], ah.x, ah.y, ah.z, ah.w, wa.z, wa.w);
        mma16816(dA[0], dA[1], dA[2], dA[3], al.x, al.y, al.z, al.w, wa.x, wa.y);
        mma16816(dB[0], dB[1], dB[2], dB[3], ah.x, ah.y, ah.z, ah.w, wb.x, wb.y);
        mma16816(dB[0], dB[1], dB[2], dB[3], ah.x, ah.y, ah.z, ah.w, wb.z, wb.w);
        mma16816(dB[0], dB[1], dB[2], dB[3], al.x, al.y, al.z, al.w, wb.x, wb.y);
    }
}
// single-tile version (layer 2)
template<int KS>
__device__ __forceinline__ void gemm1(const uint4* __restrict__ aH,
                                      const uint4* __restrict__ aL,
                                      const uint4* __restrict__ wf,
                                      int lane, float* d) {
#pragma unroll
    for (int kk = 0; kk < KS; kk++) {
        uint4 ah = aH[kk * 32 + lane];
        uint4 al = aL[kk * 32 + lane];
        uint4 wv = wf[kk * 32 + lane];
        mma16816(d[0], d[1], d[2], d[3], ah.x, ah.y, ah.z, ah.w, wv.x, wv.y);
        mma16816(d[0], d[1], d[2], d[3], ah.x, ah.y, ah.z, ah.w, wv.z, wv.w);
        mma16816(d[0], d[1], d[2], d[3], al.x, al.y, al.z, al.w, wv.x, wv.y);
    }
}

// epilogue store: values (v00,v01)=row g, (v10,v11)=row g+8 -> A-frag slot
// idx = kstep*128 + lane*4 + jb (jb even) as two uint2 (hi, lo buffers).
__device__ __forceinline__ void epi_store(float v00, float v01, float v10, float v11,
                                          uint32_t* dH, uint32_t* dL, int idx) {
    *reinterpret_cast<uint2*>(dH + idx) = make_uint2(pk2(v00, v01), pk2(v10, v11));
    *reinterpret_cast<uint2*>(dL + idx) =
        make_uint2(pk2(bflo(v00), bflo(v01)), pk2(bflo(v10), bflo(v11)));
}

// ---------------------------------------------------------------------------
__global__ void __launch_bounds__(NTHREADS, 1)
node_kernel(const float* __restrict__ y0, const float* __restrict__ ts,
            const float* __restrict__ w0, const float* __restrict__ b0,
            const float* __restrict__ w1, const float* __restrict__ b1,
            const float* __restrict__ w2, const float* __restrict__ b2,
            float* __restrict__ out, int T) {
    extern __shared__ char smem[];
    uint4* wf0 = (uint4*)(smem + O_WF0);
    uint4* wf1 = (uint4*)(smem + O_WF1);
    uint4* wf2 = (uint4*)(smem + O_WF2);
    uint32_t* a0H = (uint32_t*)(smem + O_A0H);
    uint32_t* a0L = (uint32_t*)(smem + O_A0L);
    uint32_t* a1H = (uint32_t*)(smem + O_A1H);
    uint32_t* a1L = (uint32_t*)(smem + O_A1L);
    uint32_t* a2H = (uint32_t*)(smem + O_A2H);
    uint32_t* a2L = (uint32_t*)(smem + O_A2L);
    float* kbuf = (float*)(smem + O_KB);
    float* ysh  = (float*)(smem + O_Y);

    const int tid  = threadIdx.x;
    const int lane = tid & 31;
    const int warp = tid >> 5;               // 0..7
    const int g    = lane >> 2;              // fragment row group
    const int t2   = (lane & 3) * 2;         // fragment col pair base
    const int row0 = blockIdx.x * M_TILE;

    // ---- setup: weight fragments (hi/lo bf16, mma layout) --------------------
    // entry [T][kk][l]: n = 8T+g', k0 = 16kk + 2t'; {b0h,b1h,b0l,b1l}
    for (int idx = tid; idx < 16 * 4 * 32; idx += NTHREADS) {      // L0, K=64
        int Tt = idx >> 7, kk = (idx >> 5) & 3, l = idx & 31;
        const float* wr = w0 + (8 * Tt + (l >> 2)) * 65 + 1 + 16 * kk + 2 * (l & 3);
        float v0 = wr[0], v1 = wr[1], v8 = wr[8], v9 = wr[9];
        wf0[idx] = make_uint4(pk2(v0, v1), pk2(v8, v9),
                              pk2(bflo(v0), bflo(v1)), pk2(bflo(v8), bflo(v9)));
    }
    for (int idx = tid; idx < 16 * 8 * 32; idx += NTHREADS) {      // L1, K=128
        int Tt = idx >> 8, kk = (idx >> 5) & 7, l = idx & 31;
        const float* wr = w1 + (8 * Tt + (l >> 2)) * 128 + 16 * kk + 2 * (l & 3);
        float v0 = wr[0], v1 = wr[1], v8 = wr[8], v9 = wr[9];
        wf1[idx] = make_uint4(pk2(v0, v1), pk2(v8, v9),
                              pk2(bflo(v0), bflo(v1)), pk2(bflo(v8), bflo(v9)));
    }
    for (int idx = tid; idx < 8 * 8 * 32; idx += NTHREADS) {       // L2, K=128
        int Tt = idx >> 8, kk = (idx >> 5) & 7, l = idx & 31;
        const float* wr = w2 + (8 * Tt + (l >> 2)) * 128 + 16 * kk + 2 * (l & 3);
        float v0 = wr[0], v1 = wr[1], v8 = wr[8], v9 = wr[9];
        wf2[idx] = make_uint4(pk2(v0, v1), pk2(v8, v9),
                              pk2(bflo(v0), bflo(v1)), pk2(bflo(v8), bflo(v9)));
    }
    // y0 -> ysh + initial act0 fragments
    for (int pi = tid; pi < 512; pi += NTHREADS) {
        int r = pi >> 5, p = pi & 31;
        float v0 = y0[(row0 + r) * 64 + 2 * p];
        float v1 = y0[(row0 + r) * 64 + 2 * p + 1];
        ysh[r * 64 + 2 * p] = v0; ysh[r * 64 + 2 * p + 1] = v1;
        int kstep = p >> 3, pw = p & 7;
        int lp = ((r & 7) << 2) | (pw & 3);
        int j = ((pw >> 2) << 1) | (r >> 3);
        int idx = kstep * 128 + lp * 4 + j;
        a0H[idx] = pk2(v0, v1);
        a0L[idx] = pk2(bflo(v0), bflo(v1));
    }

    // ---- hoisted per-lane bias constants -------------------------------------
    const int cA = 8 * warp + t2;            // tile "a" col base (also L2 col)
    const int cB = cA + 64;                  // tile "b" col base (warp+8)
    const float b0A0 = b0[cA], b0A1 = b0[cA + 1], b0B0 = b0[cB], b0B1 = b0[cB + 1];
    const float wcA0 = w0[cA * 65], wcA1 = w0[(cA + 1) * 65];
    const float wcB0 = w0[cB * 65], wcB1 = w0[(cB + 1) * 65];
    const float b1A0 = b1[cA], b1A1 = b1[cA + 1], b1B0 = b1[cB], b1B1 = b1[cB + 1];
    const float b2A  = b2[cA], b2B = b2[cA + 1];

    __syncthreads();

    const float dt = ts[1] - ts[0];
    const int steps = T - 1;

    const uint4* a0Hv = (const uint4*)a0H; const uint4* a0Lv = (const uint4*)a0L;
    const uint4* a1Hv = (const uint4*)a1H; const uint4* a1Lv = (const uint4*)a1L;
    const uint4* a2Hv = (const uint4*)a2H; const uint4* a2Lv = (const uint4*)a2L;
    const uint4* wf0A = wf0 + warp * 4 * 32;
    const uint4* wf0B = wf0 + (warp + 8) * 4 * 32;
    const uint4* wf1A = wf1 + warp * 8 * 32;
    const uint4* wf1B = wf1 + (warp + 8) * 8 * 32;
    const uint4* wf2W = wf2 + warp * 8 * 32;

    // epilogue A-frag indices: tile T: kstep=T>>1, jb=2*(T&1)
    const int idxA = (warp >> 1) * 128 + lane * 4 + 2 * (warp & 1);  // tile warp
    const int idxB = idxA + 4 * 128;                                 // tile warp+8

    for (int st = 0; st < steps; st++) {
        const float t = ts[st];
        for (int s = 0; s < 6; s++) {
            const float tt = fmaf(d_cs[s], dt, t);

            // ================= Layer 0 =================
            {
                float dA[4] = {0.f, 0.f, 0.f, 0.f}, dB4[4] = {0.f, 0.f, 0.f, 0.f};
                gemm2<4>(a0Hv, a0Lv, wf0A, wf0B, lane, dA, dB4);
                const float vA0 = fmaf(wcA0, tt, b0A0), vA1 = fmaf(wcA1, tt, b0A1);
                const float vB0 = fmaf(wcB0, tt, b0B0), vB1 = fmaf(wcB1, tt, b0B1);
                epi_store(fmaxf(dA[0] + vA0, 0.f), fmaxf(dA[1] + vA1, 0.f),
                          fmaxf(dA[2] + vA0, 0.f), fmaxf(dA[3] + vA1, 0.f),
                          a1H, a1L, idxA);
                epi_store(fmaxf(dB4[0] + vB0, 0.f), fmaxf(dB4[1] + vB1, 0.f),
                          fmaxf(dB4[2] + vB0, 0.f), fmaxf(dB4[3] + vB1, 0.f),
                          a1H, a1L, idxB);
            }
            __syncthreads();

            // ================= Layer 1 =================
            {
                float dA[4] = {0.f, 0.f, 0.f, 0.f}, dB4[4] = {0.f, 0.f, 0.f, 0.f};
                gemm2<8>(a1Hv, a1Lv, wf1A, wf1B, lane, dA, dB4);
                epi_store(fmaxf(dA[0] + b1A0, 0.f), fmaxf(dA[1] + b1A1, 0.f),
                          fmaxf(dA[2] + b1A0, 0.f), fmaxf(dA[3] + b1A1, 0.f),
                          a2H, a2L, idxA);
                epi_store(fmaxf(dB4[0] + b1B0, 0.f), fmaxf(dB4[1] + b1B1, 0.f),
                          fmaxf(dB4[2] + b1B0, 0.f), fmaxf(dB4[3] + b1B1, 0.f),
                          a2H, a2L, idxB);
            }
            __syncthreads();

            // ================= Layer 2 + fused RK ======
            {
                float d[4] = {0.f, 0.f, 0.f, 0.f};
                gemm1<8>(a2Hv, a2Lv, wf2W, lane, d);
                const float k00 = d[0] + b2A, k01 = d[1] + b2B;
                const float k10 = d[2] + b2A, k11 = d[3] + b2B;

                const float y00 = ysh[g * 64 + cA],       y01 = ysh[g * 64 + cA + 1];
                const float y10 = ysh[(g + 8) * 64 + cA], y11 = ysh[(g + 8) * 64 + cA + 1];
                float v00, v01, v10, v11;

                if (s < 5) {
                    // park k_s, build act0 for stage s+1
                    *(float2*)(kbuf + s * KBSTG + g * SKB + cA) = make_float2(k00, k01);
                    *(float2*)(kbuf + s * KBSTG + (g + 8) * SKB + cA) = make_float2(k10, k11);
                    const float cs = d_A[s + 1][s];
                    float a00 = cs * k00, a01 = cs * k01, a10 = cs * k10, a11 = cs * k11;
                    for (int j = 0; j < s; j++) {
                        const float cj = d_A[s + 1][j];
                        float2 p0 = *(const float2*)(kbuf + j * KBSTG + g * SKB + cA);
                        float2 p1 = *(const float2*)(kbuf + j * KBSTG + (g + 8) * SKB + cA);
                        a00 = fmaf(cj, p0.x, a00); a01 = fmaf(cj, p0.y, a01);
                        a10 = fmaf(cj, p1.x, a10); a11 = fmaf(cj, p1.y, a11);
                    }
                    v00 = fmaf(dt, a00, y00); v01 = fmaf(dt, a01, y01);
                    v10 = fmaf(dt, a10, y10); v11 = fmaf(dt, a11, y11);
                } else {
                    const float c5 = d_B[5];
                    float a00 = c5 * k00, a01 = c5 * k01, a10 = c5 * k10, a11 = c5 * k11;
#pragma unroll
                    for (int j = 0; j < 5; j++) {
                        const float cj = d_B[j];
                        float2 p0 = *(const float2*)(kbuf + j * KBSTG + g * SKB + cA);
                        float2 p1 = *(const float2*)(kbuf + j * KBSTG + (g + 8) * SKB + cA);
                        a00 = fmaf(cj, p0.x, a00); a01 = fmaf(cj, p0.y, a01);
                        a10 = fmaf(cj, p1.x, a10); a11 = fmaf(cj, p1.y, a11);
                    }
                    v00 = fmaf(dt, a00, y00); v01 = fmaf(dt, a01, y01);
                    v10 = fmaf(dt, a10, y10); v11 = fmaf(dt, a11, y11);
                    *(float2*)(ysh + g * 64 + cA)       = make_float2(v00, v01);
                    *(float2*)(ysh + (g + 8) * 64 + cA) = make_float2(v10, v11);
                    if (st == steps - 1) {
                        *(float2*)(out + (row0 + g) * 64 + cA)       = make_float2(v00, v01);
                        *(float2*)(out + (row0 + g + 8) * 64 + cA)   = make_float2(v10, v11);
                    }
                }
                // act0 fragment write: tile T=warp -> kstep=warp>>1, jb=2*(warp&1)
                epi_store(v00, v01, v10, v11, a0H, a0L, idxA);
            }
            __syncthreads();
        }
    }
}

// ---------------------------------------------------------------------------
extern "C" void kernel_launch(void* const* d_in, const int* in_sizes, int n_in,
                              void* d_out, int out_size) {
    const float* y0 = (const float*)d_in[0];
    const float* ts = (const float*)d_in[1];
    const float* w0 = (const float*)d_in[2];
    const float* b0 = (const float*)d_in[3];
    const float* w1 = (const float*)d_in[4];
    const float* b1 = (const float*)d_in[5];
    const float* w2 = (const float*)d_in[6];
    const float* b2 = (const float*)d_in[7];

    const int B = in_sizes[0] / 64;
    const int T = in_sizes[1];

    cudaFuncSetAttribute(node_kernel,
                         cudaFuncAttributeMaxDynamicSharedMemorySize, SMEM_BYTES);

    node_kernel<<<B / M_TILE, NTHREADS, SMEM_BYTES>>>(
        y0, ts, w0, b0, w1, b1, w2, b2, (float*)d_out, T);
}